// round 1
// baseline (speedup 1.0000x reference)
#include <cuda_runtime.h>
#include <math.h>

#define B_ 8
#define SQ_ 1024
#define SKV_ 1024
#define D_ 1024
#define H_ 16
#define HD_ 64

// Scratch (allocation-free rule: device globals)
__device__ float g_q  [B_*SQ_*D_];
__device__ float g_k  [B_*SKV_*D_];
__device__ float g_v  [B_*SKV_*D_];
__device__ float g_ctx[B_*SQ_*D_];
__device__ float g_o1 [B_*SQ_*D_];
__device__ float g_h  [B_*SQ_*D_];

// ---------------------------------------------------------------------------
// SGEMM: C[M,1024] = A[M,1024] @ W[1024,1024] + bias[1024]
// 128x128 block tile, BK=8, 256 threads, 8x8 per-thread micro-tile.
// ---------------------------------------------------------------------------
__global__ void __launch_bounds__(256, 1) gemm_bias_kernel(
    const float* __restrict__ A, const float* __restrict__ W,
    const float* __restrict__ bias, float* __restrict__ C)
{
    const int K = 1024, N = 1024;
    __shared__ float As[8][128];
    __shared__ float Ws[8][128];

    int tid = threadIdx.x;
    int tr = tid >> 4;          // 0..15
    int tc = tid & 15;          // 0..15
    size_t row0 = (size_t)blockIdx.y * 128;
    int col0 = blockIdx.x * 128;

    // A-tile load: 128 rows x 8 cols; thread loads one float4
    int arow = tid >> 1;            // 0..127
    int acol = (tid & 1) << 2;      // 0 or 4
    // W-tile load: 8 rows x 128 cols; thread loads one float4
    int wrow = tid >> 5;            // 0..7
    int wcol = (tid & 31) << 2;     // 0..124

    float acc[8][8];
#pragma unroll
    for (int i = 0; i < 8; i++)
#pragma unroll
        for (int j = 0; j < 8; j++) acc[i][j] = 0.f;

    const float* Aptr = A + (row0 + arow) * K + acol;
    const float* Wptr = W + (size_t)wrow * N + col0 + wcol;

    for (int kt = 0; kt < K; kt += 8) {
        float4 a4 = *(const float4*)(Aptr + kt);
        As[acol + 0][arow] = a4.x;
        As[acol + 1][arow] = a4.y;
        As[acol + 2][arow] = a4.z;
        As[acol + 3][arow] = a4.w;
        float4 w4 = *(const float4*)(Wptr + (size_t)kt * N);
        *(float4*)&Ws[wrow][wcol] = w4;
        __syncthreads();

#pragma unroll
        for (int kk = 0; kk < 8; kk++) {
            float4 a0 = *(const float4*)&As[kk][tr * 8];
            float4 a1 = *(const float4*)&As[kk][tr * 8 + 4];
            float4 w0 = *(const float4*)&Ws[kk][tc * 8];
            float4 w1 = *(const float4*)&Ws[kk][tc * 8 + 4];
            float a[8] = {a0.x, a0.y, a0.z, a0.w, a1.x, a1.y, a1.z, a1.w};
            float w[8] = {w0.x, w0.y, w0.z, w0.w, w1.x, w1.y, w1.z, w1.w};
#pragma unroll
            for (int i = 0; i < 8; i++)
#pragma unroll
                for (int j = 0; j < 8; j++)
                    acc[i][j] += a[i] * w[j];
        }
        __syncthreads();
    }

#pragma unroll
    for (int i = 0; i < 8; i++) {
        size_t row = row0 + tr * 8 + i;
#pragma unroll
        for (int j = 0; j < 8; j += 4) {
            int col = col0 + tc * 8 + j;
            float4 b4 = *(const float4*)(bias + col);
            float4 o4;
            o4.x = acc[i][j + 0] + b4.x;
            o4.y = acc[i][j + 1] + b4.y;
            o4.z = acc[i][j + 2] + b4.z;
            o4.w = acc[i][j + 3] + b4.w;
            *(float4*)(C + row * N + col) = o4;
        }
    }
}

// ---------------------------------------------------------------------------
// Flash attention: one thread per query row. Block = 256 queries of one (b,h).
// K/V staged in smem as 32x64 tiles; online softmax in registers.
// ---------------------------------------------------------------------------
__global__ void __launch_bounds__(256, 1) attn_kernel(
    const float* __restrict__ q, const float* __restrict__ k,
    const float* __restrict__ v, const int* __restrict__ mask,
    float* __restrict__ ctx)
{
    __shared__ float Ks[32][64];
    __shared__ float Vs[32][64];
    __shared__ int Ms[32];

    int b = blockIdx.z, h = blockIdx.y;
    int tid = threadIdx.x;
    int qi = blockIdx.x * 256 + tid;

    const float* qp = q + ((size_t)(b * SQ_ + qi)) * D_ + h * HD_;
    float qr[64];
#pragma unroll
    for (int i = 0; i < 16; i++) {
        float4 t4 = *(const float4*)(qp + i * 4);
        qr[i * 4 + 0] = t4.x; qr[i * 4 + 1] = t4.y;
        qr[i * 4 + 2] = t4.z; qr[i * 4 + 3] = t4.w;
    }
    float acc[64];
#pragma unroll
    for (int d = 0; d < 64; d++) acc[d] = 0.f;
    float m = -INFINITY, l = 0.f;

    int lr = tid >> 3;            // 0..31  tile row
    int lc = (tid & 7) << 3;      // 0..56  tile col (8 floats)

    for (int kv0 = 0; kv0 < SKV_; kv0 += 32) {
        __syncthreads();
        const float* kp = k + ((size_t)(b * SKV_ + kv0 + lr)) * D_ + h * HD_ + lc;
        const float* vp = v + ((size_t)(b * SKV_ + kv0 + lr)) * D_ + h * HD_ + lc;
        *(float4*)&Ks[lr][lc]     = *(const float4*)kp;
        *(float4*)&Ks[lr][lc + 4] = *(const float4*)(kp + 4);
        *(float4*)&Vs[lr][lc]     = *(const float4*)vp;
        *(float4*)&Vs[lr][lc + 4] = *(const float4*)(vp + 4);
        if (tid < 32) Ms[tid] = mask[b * SKV_ + kv0 + tid];
        __syncthreads();

        for (int j = 0; j < 32; j++) {
            if (!Ms[j]) continue;
            float s = 0.f;
#pragma unroll
            for (int d4 = 0; d4 < 16; d4++) {
                float4 k4 = *(const float4*)&Ks[j][d4 * 4];
                s += qr[d4 * 4 + 0] * k4.x + qr[d4 * 4 + 1] * k4.y
                   + qr[d4 * 4 + 2] * k4.z + qr[d4 * 4 + 3] * k4.w;
            }
            s *= 0.125f;  // 1/sqrt(64)
            if (s > m) {
                float corr = __expf(m - s);   // first key: exp(-inf)=0
                m = s;
                l *= corr;
#pragma unroll
                for (int d = 0; d < 64; d++) acc[d] *= corr;
            }
            float p = __expf(s - m);
            l += p;
#pragma unroll
            for (int d4 = 0; d4 < 16; d4++) {
                float4 v4 = *(const float4*)&Vs[j][d4 * 4];
                acc[d4 * 4 + 0] += p * v4.x; acc[d4 * 4 + 1] += p * v4.y;
                acc[d4 * 4 + 2] += p * v4.z; acc[d4 * 4 + 3] += p * v4.w;
            }
        }
    }

    float inv = 1.f / l;
    float* op = ctx + ((size_t)(b * SQ_ + qi)) * D_ + h * HD_;
#pragma unroll
    for (int d4 = 0; d4 < 16; d4++) {
        float4 o4 = make_float4(acc[d4 * 4 + 0] * inv, acc[d4 * 4 + 1] * inv,
                                acc[d4 * 4 + 2] * inv, acc[d4 * 4 + 3] * inv);
        *(float4*)(op + d4 * 4) = o4;
    }
}

// ---------------------------------------------------------------------------
// Block reduce over 256 threads (8 warps)
// ---------------------------------------------------------------------------
__device__ __forceinline__ float block_reduce_sum_256(float val, float* sbuf)
{
    int lane = threadIdx.x & 31, w = threadIdx.x >> 5;
#pragma unroll
    for (int o = 16; o; o >>= 1) val += __shfl_xor_sync(0xffffffff, val, o);
    if (lane == 0) sbuf[w] = val;
    __syncthreads();
    float r = (threadIdx.x < 8) ? sbuf[threadIdx.x] : 0.f;
    if (w == 0) {
#pragma unroll
        for (int o = 4; o; o >>= 1) r += __shfl_xor_sync(0xffffffff, r, o);
        if (lane == 0) sbuf[0] = r;
    }
    __syncthreads();
    return sbuf[0];
}

// out = LN(a + b) with gain/beta
__global__ void __launch_bounds__(256) ln_add_kernel(
    const float* __restrict__ a, const float* __restrict__ bsrc,
    const float* __restrict__ g, const float* __restrict__ beta,
    float* __restrict__ out)
{
    __shared__ float sbuf[8];
    size_t row = blockIdx.x;
    int t = threadIdx.x;
    const float* pa = a + row * 1024;
    const float* pb = bsrc + row * 1024;
    float x[4];
    float s = 0.f;
#pragma unroll
    for (int i = 0; i < 4; i++) { int idx = t + i * 256; x[i] = pa[idx] + pb[idx]; s += x[i]; }
    s = block_reduce_sum_256(s, sbuf);
    float mu = s * (1.f / 1024.f);
    float vv = 0.f;
#pragma unroll
    for (int i = 0; i < 4; i++) { float d = x[i] - mu; vv += d * d; }
    __syncthreads();
    vv = block_reduce_sum_256(vv, sbuf);
    float r = rsqrtf(vv * (1.f / 1024.f) + 1e-5f);
    float* po = out + row * 1024;
#pragma unroll
    for (int i = 0; i < 4; i++) {
        int idx = t + i * 256;
        po[idx] = (x[i] - mu) * r * g[idx] + beta[idx];
    }
}

// out = LN(a + gelu(b)) with gain/beta (exact GELU)
__global__ void __launch_bounds__(256) ln_gelu_kernel(
    const float* __restrict__ a, const float* __restrict__ bsrc,
    const float* __restrict__ g, const float* __restrict__ beta,
    float* __restrict__ out)
{
    __shared__ float sbuf[8];
    size_t row = blockIdx.x;
    int t = threadIdx.x;
    const float* pa = a + row * 1024;
    const float* pb = bsrc + row * 1024;
    float x[4];
    float s = 0.f;
#pragma unroll
    for (int i = 0; i < 4; i++) {
        int idx = t + i * 256;
        float hv = pb[idx];
        float ge = 0.5f * hv * (1.f + erff(hv * 0.70710678118654752f));
        x[i] = pa[idx] + ge;
        s += x[i];
    }
    s = block_reduce_sum_256(s, sbuf);
    float mu = s * (1.f / 1024.f);
    float vv = 0.f;
#pragma unroll
    for (int i = 0; i < 4; i++) { float d = x[i] - mu; vv += d * d; }
    __syncthreads();
    vv = block_reduce_sum_256(vv, sbuf);
    float r = rsqrtf(vv * (1.f / 1024.f) + 1e-5f);
    float* po = out + row * 1024;
#pragma unroll
    for (int i = 0; i < 4; i++) {
        int idx = t + i * 256;
        po[idx] = (x[i] - mu) * r * g[idx] + beta[idx];
    }
}

// ---------------------------------------------------------------------------
extern "C" void kernel_launch(void* const* d_in, const int* in_sizes, int n_in,
                              void* d_out, int out_size)
{
    const float* Q     = (const float*)d_in[0];
    const float* K     = (const float*)d_in[1];
    const int*   mask  = (const int*)d_in[2];
    const float* Wq    = (const float*)d_in[3];
    const float* bq    = (const float*)d_in[4];
    const float* Wk    = (const float*)d_in[5];
    const float* bk    = (const float*)d_in[6];
    const float* Wv    = (const float*)d_in[7];
    const float* bv    = (const float*)d_in[8];
    const float* Wp    = (const float*)d_in[9];
    const float* bp    = (const float*)d_in[10];
    const float* g0    = (const float*)d_in[11];
    const float* beta0 = (const float*)d_in[12];
    const float* g1    = (const float*)d_in[13];
    const float* beta1 = (const float*)d_in[14];
    float* out = (float*)d_out;

    float *q, *k, *v, *ctx, *o1, *h;
    cudaGetSymbolAddress((void**)&q,   g_q);
    cudaGetSymbolAddress((void**)&k,   g_k);
    cudaGetSymbolAddress((void**)&v,   g_v);
    cudaGetSymbolAddress((void**)&ctx, g_ctx);
    cudaGetSymbolAddress((void**)&o1,  g_o1);
    cudaGetSymbolAddress((void**)&h,   g_h);

    const int M = B_ * SQ_;  // 8192
    dim3 ggrid(1024 / 128, M / 128);  // (8, 64)
    dim3 gblk(256);

    // Input projections
    gemm_bias_kernel<<<ggrid, gblk>>>(Q, Wq, bq, q);
    gemm_bias_kernel<<<ggrid, gblk>>>(K, Wk, bk, k);
    gemm_bias_kernel<<<ggrid, gblk>>>(K, Wv, bv, v);

    // Attention
    dim3 agrid(SQ_ / 256, H_, B_);
    attn_kernel<<<agrid, 256>>>(q, k, v, mask, ctx);

    // LN1: o1 = LN(q + ctx)
    ln_add_kernel<<<M, 256>>>(q, ctx, g0, beta0, o1);

    // Output projection: h = o1 @ Wp + bp
    gemm_bias_kernel<<<ggrid, gblk>>>(o1, Wp, bp, h);

    // LN2: out = LN(o1 + gelu(h))
    ln_gelu_kernel<<<M, 256>>>(o1, h, g1, beta1, out);
}

// round 3
// speedup vs baseline: 1.7746x; 1.7746x over previous
#include <cuda_runtime.h>
#include <cuda_bf16.h>
#include <math.h>
#include <stdint.h>

#define B_ 8
#define SQ_ 1024
#define SKV_ 1024
#define D_ 1024
#define H_ 16
#define HD_ 64
#define MTOT (B_*SQ_)   // 8192

// ---------------- scratch (device globals; allocation-free rule) -----------
__device__ float g_q  [MTOT*D_];
__device__ float g_k  [MTOT*D_];
__device__ float g_v  [MTOT*D_];
__device__ float g_ctx[MTOT*D_];
__device__ float g_o1 [MTOT*D_];
__device__ float g_h  [MTOT*D_];

__device__ __nv_bfloat16 g_qh[MTOT*D_], g_ql[MTOT*D_];
__device__ __nv_bfloat16 g_kh[MTOT*D_], g_kl[MTOT*D_];
__device__ __nv_bfloat16 g_oh[MTOT*D_], g_ol[MTOT*D_];

__device__ __nv_bfloat16 g_wqh[D_*D_], g_wql[D_*D_];
__device__ __nv_bfloat16 g_wkh[D_*D_], g_wkl[D_*D_];
__device__ __nv_bfloat16 g_wvh[D_*D_], g_wvl[D_*D_];
__device__ __nv_bfloat16 g_wph[D_*D_], g_wpl[D_*D_];

// ---------------- common helpers -------------------------------------------
__device__ __forceinline__ uint32_t smem_to_u32(const void* p) {
    uint32_t a;
    asm("{ .reg .u64 t; cvta.to.shared.u64 t, %1; cvt.u32.u64 %0, t; }" : "=r"(a) : "l"(p));
    return a;
}
#define CP_ASYNC16(dst_u32, gptr) \
    asm volatile("cp.async.cg.shared.global [%0], [%1], 16;" :: "r"(dst_u32), "l"(gptr) : "memory")
#define CP_COMMIT() asm volatile("cp.async.commit_group;" ::: "memory")
#define CP_WAIT1()  asm volatile("cp.async.wait_group 1;" ::: "memory")
#define CP_WAIT0()  asm volatile("cp.async.wait_group 0;" ::: "memory")

#define LDSM_X4(r0,r1,r2,r3,addr) \
    asm volatile("ldmatrix.sync.aligned.m8n8.x4.shared.b16 {%0,%1,%2,%3}, [%4];" \
        : "=r"(r0),"=r"(r1),"=r"(r2),"=r"(r3) : "r"(addr))

#define MMA_BF16(c, a, b0v, b1v) \
    asm volatile("mma.sync.aligned.m16n8k16.row.col.f32.bf16.bf16.f32 " \
        "{%0,%1,%2,%3}, {%4,%5,%6,%7}, {%8,%9}, {%0,%1,%2,%3};" \
        : "+f"((c)[0]),"+f"((c)[1]),"+f"((c)[2]),"+f"((c)[3]) \
        : "r"((a)[0]),"r"((a)[1]),"r"((a)[2]),"r"((a)[3]), "r"(b0v),"r"(b1v))

// ---------------- tcgen05 helpers (only in 'a' feature pass) ----------------
#if defined(__CUDA_ARCH_FEAT_SM103_ALL) || defined(__CUDA_ARCH_FEAT_SM100_ALL)
#define HAS_TCGEN05 1
__device__ __forceinline__ uint32_t elect_one_pred() {
    uint32_t pred;
    asm volatile("{\n\t.reg .pred p;\n\telect.sync _|p, 0xFFFFFFFF;\n\tselp.b32 %0, 1, 0, p;\n\t}" : "=r"(pred));
    return pred;
}
#define TCGEN05_ALLOC(smem_addr, nCols) \
    asm volatile("tcgen05.alloc.cta_group::1.sync.aligned.shared::cta.b32 [%0], %1;" \
        :: "r"((uint32_t)(smem_addr)), "r"((uint32_t)(nCols)) : "memory")
#define TCGEN05_DEALLOC(tmem_addr, nCols) \
    asm volatile("tcgen05.dealloc.cta_group::1.sync.aligned.b32 %0, %1;" :: "r"(tmem_addr), "r"((uint32_t)(nCols)))
#define TCGEN05_RELINQUISH() \
    asm volatile("tcgen05.relinquish_alloc_permit.cta_group::1.sync.aligned;")
#define TCGEN05_COMMIT(mbar) \
    asm volatile("tcgen05.commit.cta_group::1.mbarrier::arrive::one.shared::cluster.b64 [%0];" \
        :: "r"((uint32_t)(mbar)) : "memory")
#define TCGEN05_FENCE_AFTER() asm volatile("tcgen05.fence::after_thread_sync;" ::: "memory")
#define TCGEN05_FENCE_BEFORE() asm volatile("tcgen05.fence::before_thread_sync;" ::: "memory")
#define TCGEN05_WAIT_LD() asm volatile("tcgen05.wait::ld.sync.aligned;" ::: "memory")
#define MBARRIER_INIT(mbar, cnt) \
    asm volatile("mbarrier.init.shared.b64 [%0], %1;" :: "r"((uint32_t)(mbar)), "r"((uint32_t)(cnt)) : "memory")
#define MBARRIER_WAIT_PARITY(mbar_smem_addr, phase_parity) do { \
    uint32_t _mbar = (uint32_t)(mbar_smem_addr); \
    uint32_t _parity = (uint32_t)(phase_parity); \
    uint32_t _done; \
    asm volatile("{\n\t.reg .pred p;\n\t" \
        "mbarrier.try_wait.parity.acquire.cta.shared::cta.b64 p, [%1], %2;\n\t" \
        "selp.b32 %0, 1, 0, p;\n\t}" : "=r"(_done) : "r"(_mbar), "r"(_parity) : "memory"); \
    if (!_done) { \
        asm volatile("{\n\t.reg .pred P1;\n\t" \
            "WAIT_LOOP_%=:\n\t" \
            "mbarrier.try_wait.parity.acquire.cta.shared::cta.b64 P1, [%0], %1, 0x989680;\n\t" \
            "@P1 bra.uni WAIT_DONE_%=;\n\t" \
            "bra.uni WAIT_LOOP_%=;\n\t" \
            "WAIT_DONE_%=:\n\t}" :: "r"(_mbar), "r"(_parity) : "memory"); \
    } \
} while(0)
#define TCGEN05_LD_32X32B_X32(r, tmem_addr) \
    asm volatile("tcgen05.ld.sync.aligned.32x32b.x32.b32 " \
        "{%0, %1, %2, %3, %4, %5, %6, %7, %8, %9, %10, %11, %12, %13, %14, %15, " \
        "%16, %17, %18, %19, %20, %21, %22, %23, %24, %25, %26, %27, %28, %29, %30, %31}, [%32];" \
        : "=r"((r)[0]),"=r"((r)[1]),"=r"((r)[2]),"=r"((r)[3]),"=r"((r)[4]),"=r"((r)[5]),"=r"((r)[6]),"=r"((r)[7]), \
          "=r"((r)[8]),"=r"((r)[9]),"=r"((r)[10]),"=r"((r)[11]),"=r"((r)[12]),"=r"((r)[13]),"=r"((r)[14]),"=r"((r)[15]), \
          "=r"((r)[16]),"=r"((r)[17]),"=r"((r)[18]),"=r"((r)[19]),"=r"((r)[20]),"=r"((r)[21]),"=r"((r)[22]),"=r"((r)[23]), \
          "=r"((r)[24]),"=r"((r)[25]),"=r"((r)[26]),"=r"((r)[27]),"=r"((r)[28]),"=r"((r)[29]),"=r"((r)[30]),"=r"((r)[31]) \
        : "r"(tmem_addr))

static constexpr uint64_t SMEM_DESC_BASE_SW128 =
    (uint64_t(2)  << 61) | (uint64_t(1) << 46) | (uint64_t(64) << 32) | (uint64_t(1) << 16);
#define MAKE_SMEM_DESC(base_addr) (SMEM_DESC_BASE_SW128 | ((uint64_t)((base_addr) >> 4) & 0x3FFF))

__device__ __forceinline__ void mma_f16_ss(uint32_t d_tmem, uint64_t a_desc, uint64_t b_desc,
                                           uint32_t idesc, bool acc) {
    uint32_t en = acc ? 1u : 0u;
    asm volatile(
        "{\n\t.reg .pred p;\n\tsetp.ne.u32 p, %5, 0;\n\t"
        "tcgen05.mma.cta_group::1.kind::f16 [%0], %1, %2, %3, {%4, %4, %4, %4}, p;\n\t}"
        :: "r"(d_tmem), "l"(a_desc), "l"(b_desc), "r"(idesc), "r"(0u), "r"(en) : "memory");
}
#endif // HAS_TCGEN05

// ---------------------------------------------------------------------------
// GEMM: C[8192,1024] = A@W + bias. A hi/lo bf16 [M][K]; W transposed hi/lo [N][K].
// Tile 128M x 128N, K-chunk 64, cp.async double buffer.
// Path A (sm_103a pass): tcgen05. Path B (plain sm_103): mma.sync bf16 HMMA.
// ---------------------------------------------------------------------------
#define TM 128
#define TN 128
#define TK 64
#define OFF_AH 0
#define OFF_AL 16384
#define OFF_BH 32768
#define OFF_BL 49152
#define STAGE_BYTES 65536
#define SMEM_BUF0 2048
#define GEMM_SMEM (SMEM_BUF0 + 2*STAGE_BYTES)   // 133120

__global__ void __launch_bounds__(256, 1) tgemm_kernel(
    const __nv_bfloat16* __restrict__ Ah, const __nv_bfloat16* __restrict__ Al,
    const __nv_bfloat16* __restrict__ Bh, const __nv_bfloat16* __restrict__ Bl,
    const float* __restrict__ bias, float* __restrict__ C)
{
    extern __shared__ char smem[];
    uint32_t sb = smem_to_u32(smem);
    int tid = threadIdx.x, wid = tid >> 5, lid = tid & 31;
    int row0 = blockIdx.y * TM;
    int col0 = blockIdx.x * TN;

    // Shared loader: one K-chunk (A hi/lo 128x64, B hi/lo 128x64) into stage buf
    auto load_chunk = [&](int buf, int kc) {
        uint32_t base = sb + SMEM_BUF0 + buf * STAGE_BYTES;
        int k0 = kc * TK;
#pragma unroll
        for (int i = 0; i < 4; i++) {
            int u = tid + i * 256;
            int r = u >> 3, c = u & 7;
            uint32_t byte = (uint32_t)(r * 128 + c * 16);
            uint32_t sw = byte ^ ((byte >> 3) & 0x70);
            const __nv_bfloat16* pa = Ah + (size_t)(row0 + r) * D_ + k0 + c * 8;
            const __nv_bfloat16* pal = Al + (size_t)(row0 + r) * D_ + k0 + c * 8;
            const __nv_bfloat16* pb = Bh + (size_t)(col0 + r) * D_ + k0 + c * 8;
            const __nv_bfloat16* pbl = Bl + (size_t)(col0 + r) * D_ + k0 + c * 8;
            CP_ASYNC16(base + OFF_AH + sw, pa);
            CP_ASYNC16(base + OFF_AL + sw, pal);
            CP_ASYNC16(base + OFF_BH + sw, pb);
            CP_ASYNC16(base + OFF_BL + sw, pbl);
        }
    };

#if defined(HAS_TCGEN05)
    // ---------------- tcgen05 path ----------------
    if (wid == 0) TCGEN05_ALLOC(sb + 0, 128);
    if (tid == 0) { MBARRIER_INIT(sb + 16, 1); MBARRIER_INIT(sb + 24, 1); }
    __syncthreads();
    uint32_t tmem;
    asm volatile("ld.shared.b32 %0, [%1];" : "=r"(tmem) : "r"(sb + 0));

    const uint32_t IDESC = (1u<<4)|(1u<<7)|(1u<<10)|((uint32_t)(TN/8)<<17)|((uint32_t)(TM/16)<<24);
    int ph0 = 0, ph1 = 0;
    load_chunk(0, 0); CP_COMMIT();
    for (int kc = 0; kc < 16; kc++) {
        int buf = kc & 1;
        if (kc + 1 < 16) {
            int nb = (kc + 1) & 1;
            if (kc + 1 >= 2) {
                if (nb == 0) { MBARRIER_WAIT_PARITY(sb + 16, ph0); ph0 ^= 1; }
                else         { MBARRIER_WAIT_PARITY(sb + 24, ph1); ph1 ^= 1; }
            }
            load_chunk(nb, kc + 1); CP_COMMIT(); CP_WAIT1();
        } else {
            CP_WAIT0();
        }
        __syncthreads();
        asm volatile("fence.proxy.async.shared::cta;" ::: "memory");
        if (wid == 0 && elect_one_pred()) {
            uint32_t base = sb + SMEM_BUF0 + buf * STAGE_BYTES;
            uint64_t dah = MAKE_SMEM_DESC(base + OFF_AH);
            uint64_t dal = MAKE_SMEM_DESC(base + OFF_AL);
            uint64_t dbh = MAKE_SMEM_DESC(base + OFF_BH);
            uint64_t dbl = MAKE_SMEM_DESC(base + OFF_BL);
#pragma unroll
            for (int ks = 0; ks < 4; ks++) {
                bool first = (kc == 0 && ks == 0);
                mma_f16_ss(tmem, dah + ks * 2, dbh + ks * 2, IDESC, !first);
                mma_f16_ss(tmem, dah + ks * 2, dbl + ks * 2, IDESC, true);
                mma_f16_ss(tmem, dal + ks * 2, dbh + ks * 2, IDESC, true);
            }
            TCGEN05_COMMIT(sb + 16 + buf * 8);
        }
    }
    MBARRIER_WAIT_PARITY(sb + 16, ph0);
    MBARRIER_WAIT_PARITY(sb + 24, ph1);
    TCGEN05_FENCE_AFTER();

    if (wid < 4) {
        size_t row = (size_t)(row0 + wid * 32 + lid);
#pragma unroll
        for (int nb = 0; nb < TN; nb += 32) {
            uint32_t r[32];
            TCGEN05_LD_32X32B_X32(r, tmem + nb);
            TCGEN05_WAIT_LD();
#pragma unroll
            for (int c = 0; c < 32; c += 4) {
                float4 o;
                o.x = __uint_as_float(r[c + 0]) + __ldg(bias + col0 + nb + c + 0);
                o.y = __uint_as_float(r[c + 1]) + __ldg(bias + col0 + nb + c + 1);
                o.z = __uint_as_float(r[c + 2]) + __ldg(bias + col0 + nb + c + 2);
                o.w = __uint_as_float(r[c + 3]) + __ldg(bias + col0 + nb + c + 3);
                *(float4*)(C + row * D_ + col0 + nb + c) = o;
            }
        }
        TCGEN05_FENCE_BEFORE();
    }
    __syncthreads();
    if (wid == 0) { TCGEN05_RELINQUISH(); TCGEN05_DEALLOC(tmem, 128); }

#else
    // ---------------- mma.sync bf16 HMMA path (plain sm_103) ----------------
    int wm = wid & 3;       // 4 warps over M: 32 rows each
    int wn = wid >> 2;      // 2 warps over N: 64 cols each

    float acc[2][8][4];
#pragma unroll
    for (int i = 0; i < 2; i++)
#pragma unroll
        for (int j = 0; j < 8; j++)
#pragma unroll
            for (int e = 0; e < 4; e++) acc[i][j][e] = 0.f;

    load_chunk(0, 0); CP_COMMIT();
    for (int kc = 0; kc < 16; kc++) {
        int buf = kc & 1;
        if (kc + 1 < 16) { load_chunk(buf ^ 1, kc + 1); CP_COMMIT(); CP_WAIT1(); }
        else             { CP_WAIT0(); }
        __syncthreads();

        uint32_t base = sb + SMEM_BUF0 + buf * STAGE_BYTES;
        uint32_t ah = base + OFF_AH, al = base + OFF_AL;
        uint32_t bh = base + OFF_BH, bl = base + OFF_BL;

#pragma unroll
        for (int ks = 0; ks < 4; ks++) {
            // A fragments (m32k16, hi+lo)
            uint32_t a_h[2][4], a_l[2][4];
#pragma unroll
            for (int mi = 0; mi < 2; mi++) {
                int rowa = wm * 32 + mi * 16 + (lid & 15);
                uint32_t byte = (uint32_t)(rowa * 128 + ks * 32 + ((lid >> 4) << 4));
                uint32_t sw = byte ^ ((byte >> 3) & 0x70);
                LDSM_X4(a_h[mi][0], a_h[mi][1], a_h[mi][2], a_h[mi][3], ah + sw);
                LDSM_X4(a_l[mi][0], a_l[mi][1], a_l[mi][2], a_l[mi][3], al + sw);
            }
            // B fragments: 4 x (n16k16) per warp; hi + lo
#pragma unroll
            for (int nj = 0; nj < 4; nj++) {
                int rowb = wn * 64 + nj * 16 + (lid & 7) + ((lid >> 4) << 3);
                uint32_t byte = (uint32_t)(rowb * 128 + ks * 32 + (((lid >> 3) & 1) << 4));
                uint32_t sw = byte ^ ((byte >> 3) & 0x70);
                uint32_t bh0, bh1, bh2, bh3, bl0, bl1, bl2, bl3;
                LDSM_X4(bh0, bh1, bh2, bh3, bh + sw);
                LDSM_X4(bl0, bl1, bl2, bl3, bl + sw);
#pragma unroll
                for (int mi = 0; mi < 2; mi++) {
                    MMA_BF16(acc[mi][2*nj],   a_h[mi], bh0, bh1);
                    MMA_BF16(acc[mi][2*nj],   a_h[mi], bl0, bl1);
                    MMA_BF16(acc[mi][2*nj],   a_l[mi], bh0, bh1);
                    MMA_BF16(acc[mi][2*nj+1], a_h[mi], bh2, bh3);
                    MMA_BF16(acc[mi][2*nj+1], a_h[mi], bl2, bl3);
                    MMA_BF16(acc[mi][2*nj+1], a_l[mi], bh2, bh3);
                }
            }
        }
        __syncthreads();
    }

    // Epilogue
#pragma unroll
    for (int mi = 0; mi < 2; mi++) {
#pragma unroll
        for (int nj = 0; nj < 8; nj++) {
            int m = row0 + wm * 32 + mi * 16 + (lid >> 2);
            int n = col0 + wn * 64 + nj * 8 + (lid & 3) * 2;
            float2 o0, o1;
            float bn0 = __ldg(bias + n), bn1 = __ldg(bias + n + 1);
            o0.x = acc[mi][nj][0] + bn0; o0.y = acc[mi][nj][1] + bn1;
            o1.x = acc[mi][nj][2] + bn0; o1.y = acc[mi][nj][3] + bn1;
            *(float2*)(C + (size_t)m * D_ + n) = o0;
            *(float2*)(C + (size_t)(m + 8) * D_ + n) = o1;
        }
    }
#endif
}

// ---------------------------------------------------------------------------
// fp32 -> bf16 hi/lo split (elementwise)
// ---------------------------------------------------------------------------
__global__ void __launch_bounds__(256) conv_hilo_kernel(
    const float4* __restrict__ src, __nv_bfloat162* __restrict__ hi,
    __nv_bfloat162* __restrict__ lo, int n4)
{
    int i = blockIdx.x * 256 + threadIdx.x;
    if (i >= n4) return;
    float4 v = src[i];
    __nv_bfloat16 h0 = __float2bfloat16(v.x);
    __nv_bfloat16 h1 = __float2bfloat16(v.y);
    __nv_bfloat16 h2 = __float2bfloat16(v.z);
    __nv_bfloat16 h3 = __float2bfloat16(v.w);
    __nv_bfloat16 l0 = __float2bfloat16(v.x - __bfloat162float(h0));
    __nv_bfloat16 l1 = __float2bfloat16(v.y - __bfloat162float(h1));
    __nv_bfloat16 l2 = __float2bfloat16(v.z - __bfloat162float(h2));
    __nv_bfloat16 l3 = __float2bfloat16(v.w - __bfloat162float(h3));
    hi[2 * i]     = __nv_bfloat162(h0, h1);
    hi[2 * i + 1] = __nv_bfloat162(h2, h3);
    lo[2 * i]     = __nv_bfloat162(l0, l1);
    lo[2 * i + 1] = __nv_bfloat162(l2, l3);
}

// ---------------------------------------------------------------------------
// Weight transpose + bf16 hi/lo: W[K][N] row-major -> Wt[N][K] hi/lo
// ---------------------------------------------------------------------------
__global__ void __launch_bounds__(256) conv_w_kernel(
    const float* __restrict__ W, __nv_bfloat16* __restrict__ th,
    __nv_bfloat16* __restrict__ tl)
{
    __shared__ float t[32][33];
    int n0 = blockIdx.x * 32, k0 = blockIdx.y * 32;
    int x = threadIdx.x, y = threadIdx.y;   // block (32, 8)
#pragma unroll
    for (int i = y; i < 32; i += 8)
        t[i][x] = W[(size_t)(k0 + i) * D_ + n0 + x];
    __syncthreads();
#pragma unroll
    for (int r = y; r < 32; r += 8) {
        float vv = t[x][r];
        __nv_bfloat16 hb = __float2bfloat16(vv);
        size_t idx = (size_t)(n0 + r) * D_ + k0 + x;
        th[idx] = hb;
        tl[idx] = __float2bfloat16(vv - __bfloat162float(hb));
    }
}

// ---------------------------------------------------------------------------
// Flash attention (fp32)
// ---------------------------------------------------------------------------
__global__ void __launch_bounds__(256, 1) attn_kernel(
    const float* __restrict__ q, const float* __restrict__ k,
    const float* __restrict__ v, const int* __restrict__ mask,
    float* __restrict__ ctx)
{
    __shared__ float Ks[32][64];
    __shared__ float Vs[32][64];
    __shared__ int Ms[32];

    int b = blockIdx.z, h = blockIdx.y;
    int tid = threadIdx.x;
    int qi = blockIdx.x * 256 + tid;

    const float* qp = q + ((size_t)(b * SQ_ + qi)) * D_ + h * HD_;
    float qr[64];
#pragma unroll
    for (int i = 0; i < 16; i++) {
        float4 t4 = *(const float4*)(qp + i * 4);
        qr[i * 4 + 0] = t4.x; qr[i * 4 + 1] = t4.y;
        qr[i * 4 + 2] = t4.z; qr[i * 4 + 3] = t4.w;
    }
    float acc[64];
#pragma unroll
    for (int d = 0; d < 64; d++) acc[d] = 0.f;
    float m = -INFINITY, l = 0.f;

    int lr = tid >> 3;
    int lc = (tid & 7) << 3;

    for (int kv0 = 0; kv0 < SKV_; kv0 += 32) {
        __syncthreads();
        const float* kp = k + ((size_t)(b * SKV_ + kv0 + lr)) * D_ + h * HD_ + lc;
        const float* vp = v + ((size_t)(b * SKV_ + kv0 + lr)) * D_ + h * HD_ + lc;
        *(float4*)&Ks[lr][lc]     = *(const float4*)kp;
        *(float4*)&Ks[lr][lc + 4] = *(const float4*)(kp + 4);
        *(float4*)&Vs[lr][lc]     = *(const float4*)vp;
        *(float4*)&Vs[lr][lc + 4] = *(const float4*)(vp + 4);
        if (tid < 32) Ms[tid] = mask[b * SKV_ + kv0 + tid];
        __syncthreads();

        for (int j = 0; j < 32; j++) {
            if (!Ms[j]) continue;
            float s = 0.f;
#pragma unroll
            for (int d4 = 0; d4 < 16; d4++) {
                float4 k4 = *(const float4*)&Ks[j][d4 * 4];
                s += qr[d4 * 4 + 0] * k4.x + qr[d4 * 4 + 1] * k4.y
                   + qr[d4 * 4 + 2] * k4.z + qr[d4 * 4 + 3] * k4.w;
            }
            s *= 0.125f;
            if (s > m) {
                float corr = __expf(m - s);
                m = s;
                l *= corr;
#pragma unroll
                for (int d = 0; d < 64; d++) acc[d] *= corr;
            }
            float p = __expf(s - m);
            l += p;
#pragma unroll
            for (int d4 = 0; d4 < 16; d4++) {
                float4 v4 = *(const float4*)&Vs[j][d4 * 4];
                acc[d4 * 4 + 0] += p * v4.x; acc[d4 * 4 + 1] += p * v4.y;
                acc[d4 * 4 + 2] += p * v4.z; acc[d4 * 4 + 3] += p * v4.w;
            }
        }
    }

    float inv = 1.f / l;
    float* op = ctx + ((size_t)(b * SQ_ + qi)) * D_ + h * HD_;
#pragma unroll
    for (int d4 = 0; d4 < 16; d4++) {
        float4 o4 = make_float4(acc[d4 * 4 + 0] * inv, acc[d4 * 4 + 1] * inv,
                                acc[d4 * 4 + 2] * inv, acc[d4 * 4 + 3] * inv);
        *(float4*)(op + d4 * 4) = o4;
    }
}

// ---------------------------------------------------------------------------
// LayerNorm kernels
// ---------------------------------------------------------------------------
__device__ __forceinline__ float block_reduce_sum_256(float val, float* sbuf)
{
    int lane = threadIdx.x & 31, w = threadIdx.x >> 5;
#pragma unroll
    for (int o = 16; o; o >>= 1) val += __shfl_xor_sync(0xffffffff, val, o);
    if (lane == 0) sbuf[w] = val;
    __syncthreads();
    float r = (threadIdx.x < 8) ? sbuf[threadIdx.x] : 0.f;
    if (w == 0) {
#pragma unroll
        for (int o = 4; o; o >>= 1) r += __shfl_xor_sync(0xffffffff, r, o);
        if (lane == 0) sbuf[0] = r;
    }
    __syncthreads();
    return sbuf[0];
}

__global__ void __launch_bounds__(256) ln_add_kernel(
    const float* __restrict__ a, const float* __restrict__ bsrc,
    const float* __restrict__ g, const float* __restrict__ beta,
    float* __restrict__ out)
{
    __shared__ float sbuf[8];
    size_t row = blockIdx.x;
    int t = threadIdx.x;
    const float* pa = a + row * 1024;
    const float* pb = bsrc + row * 1024;
    float x[4];
    float s = 0.f;
#pragma unroll
    for (int i = 0; i < 4; i++) { int idx = t + i * 256; x[i] = pa[idx] + pb[idx]; s += x[i]; }
    s = block_reduce_sum_256(s, sbuf);
    float mu = s * (1.f / 1024.f);
    float vv = 0.f;
#pragma unroll
    for (int i = 0; i < 4; i++) { float d = x[i] - mu; vv += d * d; }
    __syncthreads();
    vv = block_reduce_sum_256(vv, sbuf);
    float r = rsqrtf(vv * (1.f / 1024.f) + 1e-5f);
    float* po = out + row * 1024;
#pragma unroll
    for (int i = 0; i < 4; i++) {
        int idx = t + i * 256;
        po[idx] = (x[i] - mu) * r * g[idx] + beta[idx];
    }
}

__global__ void __launch_bounds__(256) ln_gelu_kernel(
    const float* __restrict__ a, const float* __restrict__ bsrc,
    const float* __restrict__ g, const float* __restrict__ beta,
    float* __restrict__ out)
{
    __shared__ float sbuf[8];
    size_t row = blockIdx.x;
    int t = threadIdx.x;
    const float* pa = a + row * 1024;
    const float* pb = bsrc + row * 1024;
    float x[4];
    float s = 0.f;
#pragma unroll
    for (int i = 0; i < 4; i++) {
        int idx = t + i * 256;
        float hv = pb[idx];
        float ge = 0.5f * hv * (1.f + erff(hv * 0.70710678118654752f));
        x[i] = pa[idx] + ge;
        s += x[i];
    }
    s = block_reduce_sum_256(s, sbuf);
    float mu = s * (1.f / 1024.f);
    float vv = 0.f;
#pragma unroll
    for (int i = 0; i < 4; i++) { float d = x[i] - mu; vv += d * d; }
    __syncthreads();
    vv = block_reduce_sum_256(vv, sbuf);
    float r = rsqrtf(vv * (1.f / 1024.f) + 1e-5f);
    float* po = out + row * 1024;
#pragma unroll
    for (int i = 0; i < 4; i++) {
        int idx = t + i * 256;
        po[idx] = (x[i] - mu) * r * g[idx] + beta[idx];
    }
}

// ---------------------------------------------------------------------------
extern "C" void kernel_launch(void* const* d_in, const int* in_sizes, int n_in,
                              void* d_out, int out_size)
{
    const float* Q     = (const float*)d_in[0];
    const float* K     = (const float*)d_in[1];
    const int*   mask  = (const int*)d_in[2];
    const float* Wq    = (const float*)d_in[3];
    const float* bq    = (const float*)d_in[4];
    const float* Wk    = (const float*)d_in[5];
    const float* bk    = (const float*)d_in[6];
    const float* Wv    = (const float*)d_in[7];
    const float* bv    = (const float*)d_in[8];
    const float* Wp    = (const float*)d_in[9];
    const float* bp    = (const float*)d_in[10];
    const float* g0    = (const float*)d_in[11];
    const float* beta0 = (const float*)d_in[12];
    const float* g1    = (const float*)d_in[13];
    const float* beta1 = (const float*)d_in[14];
    float* out = (float*)d_out;

    float *q, *k, *v, *ctx, *o1, *h;
    cudaGetSymbolAddress((void**)&q,   g_q);
    cudaGetSymbolAddress((void**)&k,   g_k);
    cudaGetSymbolAddress((void**)&v,   g_v);
    cudaGetSymbolAddress((void**)&ctx, g_ctx);
    cudaGetSymbolAddress((void**)&o1,  g_o1);
    cudaGetSymbolAddress((void**)&h,   g_h);

    __nv_bfloat16 *qh, *ql, *kh, *kl, *oh, *ol;
    cudaGetSymbolAddress((void**)&qh, g_qh); cudaGetSymbolAddress((void**)&ql, g_ql);
    cudaGetSymbolAddress((void**)&kh, g_kh); cudaGetSymbolAddress((void**)&kl, g_kl);
    cudaGetSymbolAddress((void**)&oh, g_oh); cudaGetSymbolAddress((void**)&ol, g_ol);
    __nv_bfloat16 *wqh, *wql, *wkh, *wkl, *wvh, *wvl, *wph, *wpl;
    cudaGetSymbolAddress((void**)&wqh, g_wqh); cudaGetSymbolAddress((void**)&wql, g_wql);
    cudaGetSymbolAddress((void**)&wkh, g_wkh); cudaGetSymbolAddress((void**)&wkl, g_wkl);
    cudaGetSymbolAddress((void**)&wvh, g_wvh); cudaGetSymbolAddress((void**)&wvl, g_wvl);
    cudaGetSymbolAddress((void**)&wph, g_wph); cudaGetSymbolAddress((void**)&wpl, g_wpl);

    cudaFuncSetAttribute(tgemm_kernel, cudaFuncAttributeMaxDynamicSharedMemorySize, GEMM_SMEM);

    const int n4 = MTOT * D_ / 4;
    dim3 cblk(256);
    dim3 cgrid(n4 / 256);

    conv_hilo_kernel<<<cgrid, cblk>>>((const float4*)Q, (__nv_bfloat162*)qh, (__nv_bfloat162*)ql, n4);
    conv_hilo_kernel<<<cgrid, cblk>>>((const float4*)K, (__nv_bfloat162*)kh, (__nv_bfloat162*)kl, n4);

    dim3 wgrid(32, 32), wblk(32, 8);
    conv_w_kernel<<<wgrid, wblk>>>(Wq, wqh, wql);
    conv_w_kernel<<<wgrid, wblk>>>(Wk, wkh, wkl);
    conv_w_kernel<<<wgrid, wblk>>>(Wv, wvh, wvl);
    conv_w_kernel<<<wgrid, wblk>>>(Wp, wph, wpl);

    dim3 ggrid(D_ / TN, MTOT / TM);   // (8, 64)
    tgemm_kernel<<<ggrid, 256, GEMM_SMEM>>>(qh, ql, wqh, wql, bq, q);
    tgemm_kernel<<<ggrid, 256, GEMM_SMEM>>>(kh, kl, wkh, wkl, bk, k);
    tgemm_kernel<<<ggrid, 256, GEMM_SMEM>>>(kh, kl, wvh, wvl, bv, v);

    dim3 agrid(SQ_ / 256, H_, B_);
    attn_kernel<<<agrid, 256>>>(q, k, v, mask, ctx);

    ln_add_kernel<<<MTOT, 256>>>(q, ctx, g0, beta0, o1);

    conv_hilo_kernel<<<cgrid, cblk>>>((const float4*)o1, (__nv_bfloat162*)oh, (__nv_bfloat162*)ol, n4);
    tgemm_kernel<<<ggrid, 256, GEMM_SMEM>>>(oh, ol, wph, wpl, bp, h);

    ln_gelu_kernel<<<MTOT, 256>>>(o1, h, g1, beta1, out);
}

// round 4
// speedup vs baseline: 3.4889x; 1.9661x over previous
#include <cuda_runtime.h>
#include <cuda_bf16.h>
#include <math.h>
#include <stdint.h>

#define B_ 8
#define SQ_ 1024
#define SKV_ 1024
#define D_ 1024
#define H_ 16
#define HD_ 64
#define MTOT (B_*SQ_)   // 8192

// ---------------- scratch (device globals; allocation-free rule) -----------
__device__ float g_q  [MTOT*D_];
__device__ float g_v  [MTOT*D_];
__device__ float g_ctx[MTOT*D_];
__device__ float g_o1 [MTOT*D_];
__device__ float g_h  [MTOT*D_];

// converted inputs (GEMM A operands)
__device__ __nv_bfloat16 g_iqh[MTOT*D_], g_iql[MTOT*D_];
__device__ __nv_bfloat16 g_ikh[MTOT*D_], g_ikl[MTOT*D_];
// projected activations for attention (bf16 hi/lo)
__device__ __nv_bfloat16 g_pqh[MTOT*D_], g_pql[MTOT*D_];
__device__ __nv_bfloat16 g_pkh[MTOT*D_], g_pkl[MTOT*D_];
__device__ __nv_bfloat16 g_vth[MTOT*D_], g_vtl[MTOT*D_];   // V^T [B,H,64,Skv]
// o1 bf16 for final GEMM
__device__ __nv_bfloat16 g_o1h[MTOT*D_], g_o1l[MTOT*D_];
// weights transposed hi/lo
__device__ __nv_bfloat16 g_wqh[D_*D_], g_wql[D_*D_];
__device__ __nv_bfloat16 g_wkh[D_*D_], g_wkl[D_*D_];
__device__ __nv_bfloat16 g_wvh[D_*D_], g_wvl[D_*D_];
__device__ __nv_bfloat16 g_wph[D_*D_], g_wpl[D_*D_];

// ---------------- helpers ----------------------------------------------------
__device__ __forceinline__ uint32_t smem_to_u32(const void* p) {
    uint32_t a;
    asm("{ .reg .u64 t; cvta.to.shared.u64 t, %1; cvt.u32.u64 %0, t; }" : "=r"(a) : "l"(p));
    return a;
}
#define CP_ASYNC16(dst_u32, gptr) \
    asm volatile("cp.async.cg.shared.global [%0], [%1], 16;" :: "r"(dst_u32), "l"(gptr) : "memory")
#define CP_COMMIT() asm volatile("cp.async.commit_group;" ::: "memory")
#define CP_WAIT1()  asm volatile("cp.async.wait_group 1;" ::: "memory")
#define CP_WAIT0()  asm volatile("cp.async.wait_group 0;" ::: "memory")

#define LDSM_X4(r0,r1,r2,r3,addr) \
    asm volatile("ldmatrix.sync.aligned.m8n8.x4.shared.b16 {%0,%1,%2,%3}, [%4];" \
        : "=r"(r0),"=r"(r1),"=r"(r2),"=r"(r3) : "r"(addr))

#define MMA_BF16(c, a, b0v, b1v) \
    asm volatile("mma.sync.aligned.m16n8k16.row.col.f32.bf16.bf16.f32 " \
        "{%0,%1,%2,%3}, {%4,%5,%6,%7}, {%8,%9}, {%0,%1,%2,%3};" \
        : "+f"((c)[0]),"+f"((c)[1]),"+f"((c)[2]),"+f"((c)[3]) \
        : "r"((a)[0]),"r"((a)[1]),"r"((a)[2]),"r"((a)[3]), "r"(b0v),"r"(b1v))

__device__ __forceinline__ uint32_t pack_bf2(float x, float y) {
    __nv_bfloat162 t(__float2bfloat16(x), __float2bfloat16(y));
    return *reinterpret_cast<uint32_t*>(&t);
}

// ---------------------------------------------------------------------------
// GEMM: C = A@W + bias. A hi/lo [M][K]; W transposed hi/lo [N][K].
// Tile 128x128, K-chunk 64, cp.async double buffer, mma.sync bf16 3-term hi/lo.
// Optional fp32 output Cf and bf16 hi/lo outputs Ch/Cl.
// ---------------------------------------------------------------------------
#define TM 128
#define TN 128
#define TK 64
#define OFF_AH 0
#define OFF_AL 16384
#define OFF_BH 32768
#define OFF_BL 49152
#define STAGE_BYTES 65536
#define SMEM_BUF0 1024
#define GEMM_SMEM (SMEM_BUF0 + 2*STAGE_BYTES)

__global__ void __launch_bounds__(256, 1) tgemm_kernel(
    const __nv_bfloat16* __restrict__ Ah, const __nv_bfloat16* __restrict__ Al,
    const __nv_bfloat16* __restrict__ Bh, const __nv_bfloat16* __restrict__ Bl,
    const float* __restrict__ bias, float* __restrict__ Cf,
    __nv_bfloat16* __restrict__ Ch, __nv_bfloat16* __restrict__ Cl)
{
    extern __shared__ char smem[];
    uint32_t sb = smem_to_u32(smem);
    int tid = threadIdx.x, wid = tid >> 5, lid = tid & 31;
    int row0 = blockIdx.y * TM;
    int col0 = blockIdx.x * TN;

    auto load_chunk = [&](int buf, int kc) {
        uint32_t base = sb + SMEM_BUF0 + buf * STAGE_BYTES;
        int k0 = kc * TK;
#pragma unroll
        for (int i = 0; i < 4; i++) {
            int u = tid + i * 256;
            int r = u >> 3, c = u & 7;
            uint32_t byte = (uint32_t)(r * 128 + c * 16);
            uint32_t sw = byte ^ ((byte >> 3) & 0x70);
            CP_ASYNC16(base + OFF_AH + sw, Ah + (size_t)(row0 + r) * D_ + k0 + c * 8);
            CP_ASYNC16(base + OFF_AL + sw, Al + (size_t)(row0 + r) * D_ + k0 + c * 8);
            CP_ASYNC16(base + OFF_BH + sw, Bh + (size_t)(col0 + r) * D_ + k0 + c * 8);
            CP_ASYNC16(base + OFF_BL + sw, Bl + (size_t)(col0 + r) * D_ + k0 + c * 8);
        }
    };

    int wm = wid & 3;
    int wn = wid >> 2;

    float acc[2][8][4];
#pragma unroll
    for (int i = 0; i < 2; i++)
#pragma unroll
        for (int j = 0; j < 8; j++)
#pragma unroll
            for (int e = 0; e < 4; e++) acc[i][j][e] = 0.f;

    load_chunk(0, 0); CP_COMMIT();
    for (int kc = 0; kc < 16; kc++) {
        int buf = kc & 1;
        if (kc + 1 < 16) { load_chunk(buf ^ 1, kc + 1); CP_COMMIT(); CP_WAIT1(); }
        else             { CP_WAIT0(); }
        __syncthreads();

        uint32_t base = sb + SMEM_BUF0 + buf * STAGE_BYTES;
        uint32_t ah = base + OFF_AH, al = base + OFF_AL;
        uint32_t bh = base + OFF_BH, bl = base + OFF_BL;

#pragma unroll
        for (int ks = 0; ks < 4; ks++) {
            uint32_t a_h[2][4], a_l[2][4];
#pragma unroll
            for (int mi = 0; mi < 2; mi++) {
                int rowa = wm * 32 + mi * 16 + (lid & 15);
                uint32_t byte = (uint32_t)(rowa * 128 + ks * 32 + ((lid >> 4) << 4));
                uint32_t sw = byte ^ ((byte >> 3) & 0x70);
                LDSM_X4(a_h[mi][0], a_h[mi][1], a_h[mi][2], a_h[mi][3], ah + sw);
                LDSM_X4(a_l[mi][0], a_l[mi][1], a_l[mi][2], a_l[mi][3], al + sw);
            }
#pragma unroll
            for (int nj = 0; nj < 4; nj++) {
                int rowb = wn * 64 + nj * 16 + (lid & 7) + ((lid >> 4) << 3);
                uint32_t byte = (uint32_t)(rowb * 128 + ks * 32 + (((lid >> 3) & 1) << 4));
                uint32_t sw = byte ^ ((byte >> 3) & 0x70);
                uint32_t bh0, bh1, bh2, bh3, bl0, bl1, bl2, bl3;
                LDSM_X4(bh0, bh1, bh2, bh3, bh + sw);
                LDSM_X4(bl0, bl1, bl2, bl3, bl + sw);
#pragma unroll
                for (int mi = 0; mi < 2; mi++) {
                    MMA_BF16(acc[mi][2*nj],   a_h[mi], bh0, bh1);
                    MMA_BF16(acc[mi][2*nj],   a_h[mi], bl0, bl1);
                    MMA_BF16(acc[mi][2*nj],   a_l[mi], bh0, bh1);
                    MMA_BF16(acc[mi][2*nj+1], a_h[mi], bh2, bh3);
                    MMA_BF16(acc[mi][2*nj+1], a_h[mi], bl2, bl3);
                    MMA_BF16(acc[mi][2*nj+1], a_l[mi], bh2, bh3);
                }
            }
        }
        __syncthreads();
    }

#pragma unroll
    for (int mi = 0; mi < 2; mi++) {
#pragma unroll
        for (int nj = 0; nj < 8; nj++) {
            int m = row0 + wm * 32 + mi * 16 + (lid >> 2);
            int n = col0 + wn * 64 + nj * 8 + (lid & 3) * 2;
            float bn0 = __ldg(bias + n), bn1 = __ldg(bias + n + 1);
            float v00 = acc[mi][nj][0] + bn0, v01 = acc[mi][nj][1] + bn1;
            float v10 = acc[mi][nj][2] + bn0, v11 = acc[mi][nj][3] + bn1;
            if (Cf) {
                *(float2*)(Cf + (size_t)m * D_ + n) = make_float2(v00, v01);
                *(float2*)(Cf + (size_t)(m + 8) * D_ + n) = make_float2(v10, v11);
            }
            if (Ch) {
                uint32_t h0 = pack_bf2(v00, v01);
                uint32_t h1 = pack_bf2(v10, v11);
                *(uint32_t*)(Ch + (size_t)m * D_ + n) = h0;
                *(uint32_t*)(Ch + (size_t)(m + 8) * D_ + n) = h1;
                __nv_bfloat162 hh0 = *reinterpret_cast<__nv_bfloat162*>(&h0);
                __nv_bfloat162 hh1 = *reinterpret_cast<__nv_bfloat162*>(&h1);
                uint32_t l0 = pack_bf2(v00 - __bfloat162float(hh0.x), v01 - __bfloat162float(hh0.y));
                uint32_t l1 = pack_bf2(v10 - __bfloat162float(hh1.x), v11 - __bfloat162float(hh1.y));
                *(uint32_t*)(Cl + (size_t)m * D_ + n) = l0;
                *(uint32_t*)(Cl + (size_t)(m + 8) * D_ + n) = l1;
            }
        }
    }
}

// ---------------------------------------------------------------------------
// Tensor-core flash attention: CTA = 128 queries x one (b,h), 8 warps.
// S = Q K^T (3-term hi/lo mma), online softmax in regs, ctx += P V (3-term).
// ---------------------------------------------------------------------------
#define AOFF_QH 0
#define AOFF_QL 16384
#define AOFF_STAGE 32768
#define ASTAGE_BYTES 32768
#define ATT_SMEM (32768 + 2*ASTAGE_BYTES + 512)

__global__ void __launch_bounds__(256, 1) attn_mma_kernel(
    const __nv_bfloat16* __restrict__ pqh, const __nv_bfloat16* __restrict__ pql,
    const __nv_bfloat16* __restrict__ pkh, const __nv_bfloat16* __restrict__ pkl,
    const __nv_bfloat16* __restrict__ vth, const __nv_bfloat16* __restrict__ vtl,
    const int* __restrict__ mask, float* __restrict__ ctxout)
{
    extern __shared__ char smem[];
    uint32_t sb = smem_to_u32(smem);
    int* msm = (int*)(smem + AOFF_STAGE + 2 * ASTAGE_BYTES);   // [2][64]

    int b = blockIdx.z, h = blockIdx.y;
    int q0 = blockIdx.x * 128;
    int tid = threadIdx.x, wid = tid >> 5, lid = tid & 31;

    // Q tiles (128 x 64 hi/lo) via cp.async
#pragma unroll
    for (int i = 0; i < 4; i++) {
        int u = tid + i * 256;
        int r = u >> 3, c = u & 7;
        uint32_t byte = (uint32_t)(r * 128 + c * 16);
        uint32_t sw = byte ^ ((byte >> 3) & 0x70);
        CP_ASYNC16(sb + AOFF_QH + sw, pqh + (size_t)(b * SQ_ + q0 + r) * D_ + h * HD_ + c * 8);
        CP_ASYNC16(sb + AOFF_QL + sw, pql + (size_t)(b * SQ_ + q0 + r) * D_ + h * HD_ + c * 8);
    }

    auto load_stage = [&](int buf, int kt) {
        uint32_t base = sb + AOFF_STAGE + buf * ASTAGE_BYTES;
        int kv0 = kt * 64;
#pragma unroll
        for (int i = 0; i < 2; i++) {
            int u = tid + i * 256;
            int r = u >> 3, c = u & 7;
            uint32_t byte = (uint32_t)(r * 128 + c * 16);
            uint32_t sw = byte ^ ((byte >> 3) & 0x70);
            CP_ASYNC16(base + 0     + sw, pkh + (size_t)(b * SKV_ + kv0 + r) * D_ + h * HD_ + c * 8);
            CP_ASYNC16(base + 8192  + sw, pkl + (size_t)(b * SKV_ + kv0 + r) * D_ + h * HD_ + c * 8);
            CP_ASYNC16(base + 16384 + sw, vth + ((size_t)(b * H_ + h) * HD_ + r) * SKV_ + kv0 + c * 8);
            CP_ASYNC16(base + 24576 + sw, vtl + ((size_t)(b * H_ + h) * HD_ + r) * SKV_ + kv0 + c * 8);
        }
        if (tid < 64) msm[buf * 64 + tid] = mask[b * SKV_ + kv0 + tid];
    };

    load_stage(0, 0);
    CP_COMMIT();                      // group: Q + stage0

    uint32_t qfh[4][4], qfl[4][4];
    float ctx[8][4];
#pragma unroll
    for (int t = 0; t < 8; t++)
#pragma unroll
        for (int e = 0; e < 4; e++) ctx[t][e] = 0.f;
    float rm0 = -1e30f, rm1 = -1e30f, rl0 = 0.f, rl1 = 0.f;

    for (int kt = 0; kt < 16; kt++) {
        int buf = kt & 1;
        __syncthreads();              // protect buffer (kt+1)&1 from compute(kt-1) readers
        if (kt + 1 < 16) { load_stage(buf ^ 1, kt + 1); CP_COMMIT(); CP_WAIT1(); }
        else             { CP_WAIT0(); }
        __syncthreads();

        if (kt == 0) {
            // build Q fragments once
#pragma unroll
            for (int ks = 0; ks < 4; ks++) {
                int rowa = wid * 16 + (lid & 15);
                uint32_t byte = (uint32_t)(rowa * 128 + ks * 32 + ((lid >> 4) << 4));
                uint32_t sw = byte ^ ((byte >> 3) & 0x70);
                LDSM_X4(qfh[ks][0], qfh[ks][1], qfh[ks][2], qfh[ks][3], sb + AOFF_QH + sw);
                LDSM_X4(qfl[ks][0], qfl[ks][1], qfl[ks][2], qfl[ks][3], sb + AOFF_QL + sw);
            }
        }

        uint32_t base = sb + AOFF_STAGE + buf * ASTAGE_BYTES;
        // ---- S = Q K^T ----
        float sacc[8][4];
#pragma unroll
        for (int t = 0; t < 8; t++)
#pragma unroll
            for (int e = 0; e < 4; e++) sacc[t][e] = 0.f;

#pragma unroll
        for (int ks = 0; ks < 4; ks++) {
#pragma unroll
            for (int nj = 0; nj < 4; nj++) {
                int rowb = nj * 16 + (lid & 7) + ((lid >> 4) << 3);
                uint32_t byte = (uint32_t)(rowb * 128 + ks * 32 + (((lid >> 3) & 1) << 4));
                uint32_t sw = byte ^ ((byte >> 3) & 0x70);
                uint32_t k0, k1, k2, k3, l0, l1, l2, l3;
                LDSM_X4(k0, k1, k2, k3, base + 0 + sw);
                LDSM_X4(l0, l1, l2, l3, base + 8192 + sw);
                MMA_BF16(sacc[2*nj],   qfh[ks], k0, k1);
                MMA_BF16(sacc[2*nj],   qfh[ks], l0, l1);
                MMA_BF16(sacc[2*nj],   qfl[ks], k0, k1);
                MMA_BF16(sacc[2*nj+1], qfh[ks], k2, k3);
                MMA_BF16(sacc[2*nj+1], qfh[ks], l2, l3);
                MMA_BF16(sacc[2*nj+1], qfl[ks], k2, k3);
            }
        }

        // ---- scale + mask + online softmax ----
        const int* mrow = msm + buf * 64;
        float mx0 = -1e30f, mx1 = -1e30f;
#pragma unroll
        for (int t = 0; t < 8; t++) {
            int cb = t * 8 + (lid & 3) * 2;
            bool k0 = mrow[cb] != 0, k1 = mrow[cb + 1] != 0;
            float s00 = k0 ? sacc[t][0] * 0.125f : -1e30f;
            float s01 = k1 ? sacc[t][1] * 0.125f : -1e30f;
            float s10 = k0 ? sacc[t][2] * 0.125f : -1e30f;
            float s11 = k1 ? sacc[t][3] * 0.125f : -1e30f;
            sacc[t][0] = s00; sacc[t][1] = s01; sacc[t][2] = s10; sacc[t][3] = s11;
            mx0 = fmaxf(mx0, fmaxf(s00, s01));
            mx1 = fmaxf(mx1, fmaxf(s10, s11));
        }
        mx0 = fmaxf(mx0, __shfl_xor_sync(0xffffffffu, mx0, 1));
        mx0 = fmaxf(mx0, __shfl_xor_sync(0xffffffffu, mx0, 2));
        mx1 = fmaxf(mx1, __shfl_xor_sync(0xffffffffu, mx1, 1));
        mx1 = fmaxf(mx1, __shfl_xor_sync(0xffffffffu, mx1, 2));

        float mn0 = fmaxf(rm0, mx0), mn1 = fmaxf(rm1, mx1);
        float sc0 = __expf(rm0 - mn0), sc1 = __expf(rm1 - mn1);
        rm0 = mn0; rm1 = mn1;
        float ps0 = 0.f, ps1 = 0.f;
#pragma unroll
        for (int t = 0; t < 8; t++) {
            float p00 = __expf(sacc[t][0] - mn0);
            float p01 = __expf(sacc[t][1] - mn0);
            float p10 = __expf(sacc[t][2] - mn1);
            float p11 = __expf(sacc[t][3] - mn1);
            sacc[t][0] = p00; sacc[t][1] = p01; sacc[t][2] = p10; sacc[t][3] = p11;
            ps0 += p00 + p01;
            ps1 += p10 + p11;
            ctx[t][0] *= sc0; ctx[t][1] *= sc0;
            ctx[t][2] *= sc1; ctx[t][3] *= sc1;
        }
        ps0 += __shfl_xor_sync(0xffffffffu, ps0, 1);
        ps0 += __shfl_xor_sync(0xffffffffu, ps0, 2);
        ps1 += __shfl_xor_sync(0xffffffffu, ps1, 1);
        ps1 += __shfl_xor_sync(0xffffffffu, ps1, 2);
        rl0 = rl0 * sc0 + ps0;
        rl1 = rl1 * sc1 + ps1;

        // ---- P fragments (hi/lo) ----
        uint32_t pfh[4][4], pfl[4][4];
#pragma unroll
        for (int j = 0; j < 4; j++) {
            float p00 = sacc[2*j][0],   p01 = sacc[2*j][1];
            float p10 = sacc[2*j][2],   p11 = sacc[2*j][3];
            float q00 = sacc[2*j+1][0], q01 = sacc[2*j+1][1];
            float q10 = sacc[2*j+1][2], q11 = sacc[2*j+1][3];
            uint32_t h0 = pack_bf2(p00, p01), h1 = pack_bf2(p10, p11);
            uint32_t h2 = pack_bf2(q00, q01), h3 = pack_bf2(q10, q11);
            pfh[j][0] = h0; pfh[j][1] = h1; pfh[j][2] = h2; pfh[j][3] = h3;
            __nv_bfloat162 b0 = *reinterpret_cast<__nv_bfloat162*>(&h0);
            __nv_bfloat162 b1 = *reinterpret_cast<__nv_bfloat162*>(&h1);
            __nv_bfloat162 b2 = *reinterpret_cast<__nv_bfloat162*>(&h2);
            __nv_bfloat162 b3 = *reinterpret_cast<__nv_bfloat162*>(&h3);
            pfl[j][0] = pack_bf2(p00 - __bfloat162float(b0.x), p01 - __bfloat162float(b0.y));
            pfl[j][1] = pack_bf2(p10 - __bfloat162float(b1.x), p11 - __bfloat162float(b1.y));
            pfl[j][2] = pack_bf2(q00 - __bfloat162float(b2.x), q01 - __bfloat162float(b2.y));
            pfl[j][3] = pack_bf2(q10 - __bfloat162float(b3.x), q11 - __bfloat162float(b3.y));
        }

        // ---- ctx += P V ----
#pragma unroll
        for (int ks = 0; ks < 4; ks++) {
#pragma unroll
            for (int nj = 0; nj < 4; nj++) {
                int rowb = nj * 16 + (lid & 7) + ((lid >> 4) << 3);
                uint32_t byte = (uint32_t)(rowb * 128 + ks * 32 + (((lid >> 3) & 1) << 4));
                uint32_t sw = byte ^ ((byte >> 3) & 0x70);
                uint32_t v0, v1, v2, v3, w0, w1, w2, w3;
                LDSM_X4(v0, v1, v2, v3, base + 16384 + sw);
                LDSM_X4(w0, w1, w2, w3, base + 24576 + sw);
                MMA_BF16(ctx[2*nj],   pfh[ks], v0, v1);
                MMA_BF16(ctx[2*nj],   pfh[ks], w0, w1);
                MMA_BF16(ctx[2*nj],   pfl[ks], v0, v1);
                MMA_BF16(ctx[2*nj+1], pfh[ks], v2, v3);
                MMA_BF16(ctx[2*nj+1], pfh[ks], w2, w3);
                MMA_BF16(ctx[2*nj+1], pfl[ks], v2, v3);
            }
        }
    }

    // ---- epilogue ----
    float inv0 = 1.f / rl0, inv1 = 1.f / rl1;
    int row = q0 + wid * 16 + (lid >> 2);
#pragma unroll
    for (int t = 0; t < 8; t++) {
        int col = h * HD_ + t * 8 + (lid & 3) * 2;
        *(float2*)(ctxout + (size_t)(b * SQ_ + row) * D_ + col) =
            make_float2(ctx[t][0] * inv0, ctx[t][1] * inv0);
        *(float2*)(ctxout + (size_t)(b * SQ_ + row + 8) * D_ + col) =
            make_float2(ctx[t][2] * inv1, ctx[t][3] * inv1);
    }
}

// ---------------------------------------------------------------------------
// fp32 -> bf16 hi/lo split (elementwise)
// ---------------------------------------------------------------------------
__global__ void __launch_bounds__(256) conv_hilo_kernel(
    const float4* __restrict__ src, __nv_bfloat162* __restrict__ hi,
    __nv_bfloat162* __restrict__ lo, int n4)
{
    int i = blockIdx.x * 256 + threadIdx.x;
    if (i >= n4) return;
    float4 v = src[i];
    __nv_bfloat16 h0 = __float2bfloat16(v.x);
    __nv_bfloat16 h1 = __float2bfloat16(v.y);
    __nv_bfloat16 h2 = __float2bfloat16(v.z);
    __nv_bfloat16 h3 = __float2bfloat16(v.w);
    hi[2 * i]     = __nv_bfloat162(h0, h1);
    hi[2 * i + 1] = __nv_bfloat162(h2, h3);
    lo[2 * i]     = __nv_bfloat162(__float2bfloat16(v.x - __bfloat162float(h0)),
                                   __float2bfloat16(v.y - __bfloat162float(h1)));
    lo[2 * i + 1] = __nv_bfloat162(__float2bfloat16(v.z - __bfloat162float(h2)),
                                   __float2bfloat16(v.w - __bfloat162float(h3)));
}

// ---------------------------------------------------------------------------
// Weight transpose + bf16 hi/lo: W[K][N] -> Wt[N][K] hi/lo
// ---------------------------------------------------------------------------
__global__ void __launch_bounds__(256) conv_w_kernel(
    const float* __restrict__ W, __nv_bfloat16* __restrict__ th,
    __nv_bfloat16* __restrict__ tl)
{
    __shared__ float t[32][33];
    int n0 = blockIdx.x * 32, k0 = blockIdx.y * 32;
    int x = threadIdx.x, y = threadIdx.y;
#pragma unroll
    for (int i = y; i < 32; i += 8)
        t[i][x] = W[(size_t)(k0 + i) * D_ + n0 + x];
    __syncthreads();
#pragma unroll
    for (int r = y; r < 32; r += 8) {
        float vv = t[x][r];
        __nv_bfloat16 hb = __float2bfloat16(vv);
        size_t idx = (size_t)(n0 + r) * D_ + k0 + x;
        th[idx] = hb;
        tl[idx] = __float2bfloat16(vv - __bfloat162float(hb));
    }
}

// ---------------------------------------------------------------------------
// V transpose + hi/lo: v fp32 [B,S,D] -> vt hi/lo [B,H,64,Skv]
// ---------------------------------------------------------------------------
__global__ void __launch_bounds__(256) vtrans_kernel(
    const float* __restrict__ v, __nv_bfloat16* __restrict__ vth,
    __nv_bfloat16* __restrict__ vtl)
{
    __shared__ float t[32][33];
    int b = blockIdx.z;
    int hh = blockIdx.y;                 // 0..31: h = hh>>1, hd half
    int h = hh >> 1, hd0 = (hh & 1) * 32;
    int s0 = blockIdx.x * 32;
    int x = threadIdx.x, y = threadIdx.y;
#pragma unroll
    for (int i = y; i < 32; i += 8)
        t[i][x] = v[(size_t)(b * SQ_ + s0 + i) * D_ + h * HD_ + hd0 + x];
    __syncthreads();
#pragma unroll
    for (int r = y; r < 32; r += 8) {
        float vv = t[x][r];               // v[s0+x][hd0+r]
        __nv_bfloat16 hb = __float2bfloat16(vv);
        size_t idx = ((size_t)(b * H_ + h) * HD_ + hd0 + r) * SKV_ + s0 + x;
        vth[idx] = hb;
        vtl[idx] = __float2bfloat16(vv - __bfloat162float(hb));
    }
}

// ---------------------------------------------------------------------------
// LayerNorm kernels
// ---------------------------------------------------------------------------
__device__ __forceinline__ float block_reduce_sum_256(float val, float* sbuf)
{
    int lane = threadIdx.x & 31, w = threadIdx.x >> 5;
#pragma unroll
    for (int o = 16; o; o >>= 1) val += __shfl_xor_sync(0xffffffff, val, o);
    if (lane == 0) sbuf[w] = val;
    __syncthreads();
    float r = (threadIdx.x < 8) ? sbuf[threadIdx.x] : 0.f;
    if (w == 0) {
#pragma unroll
        for (int o = 4; o; o >>= 1) r += __shfl_xor_sync(0xffffffff, r, o);
        if (lane == 0) sbuf[0] = r;
    }
    __syncthreads();
    return sbuf[0];
}

// out = LN(a + b), also emit bf16 hi/lo of out
__global__ void __launch_bounds__(256) ln_add_kernel(
    const float* __restrict__ a, const float* __restrict__ bsrc,
    const float* __restrict__ g, const float* __restrict__ beta,
    float* __restrict__ out, __nv_bfloat16* __restrict__ outh,
    __nv_bfloat16* __restrict__ outl)
{
    __shared__ float sbuf[8];
    size_t row = blockIdx.x;
    int t = threadIdx.x;
    const float* pa = a + row * 1024;
    const float* pb = bsrc + row * 1024;
    float x[4];
    float s = 0.f;
#pragma unroll
    for (int i = 0; i < 4; i++) { int idx = t + i * 256; x[i] = pa[idx] + pb[idx]; s += x[i]; }
    s = block_reduce_sum_256(s, sbuf);
    float mu = s * (1.f / 1024.f);
    float vv = 0.f;
#pragma unroll
    for (int i = 0; i < 4; i++) { float d = x[i] - mu; vv += d * d; }
    __syncthreads();
    vv = block_reduce_sum_256(vv, sbuf);
    float r = rsqrtf(vv * (1.f / 1024.f) + 1e-5f);
#pragma unroll
    for (int i = 0; i < 4; i++) {
        int idx = t + i * 256;
        float y = (x[i] - mu) * r * g[idx] + beta[idx];
        out[row * 1024 + idx] = y;
        __nv_bfloat16 hb = __float2bfloat16(y);
        outh[row * 1024 + idx] = hb;
        outl[row * 1024 + idx] = __float2bfloat16(y - __bfloat162float(hb));
    }
}

__global__ void __launch_bounds__(256) ln_gelu_kernel(
    const float* __restrict__ a, const float* __restrict__ bsrc,
    const float* __restrict__ g, const float* __restrict__ beta,
    float* __restrict__ out)
{
    __shared__ float sbuf[8];
    size_t row = blockIdx.x;
    int t = threadIdx.x;
    const float* pa = a + row * 1024;
    const float* pb = bsrc + row * 1024;
    float x[4];
    float s = 0.f;
#pragma unroll
    for (int i = 0; i < 4; i++) {
        int idx = t + i * 256;
        float hv = pb[idx];
        float ge = 0.5f * hv * (1.f + erff(hv * 0.70710678118654752f));
        x[i] = pa[idx] + ge;
        s += x[i];
    }
    s = block_reduce_sum_256(s, sbuf);
    float mu = s * (1.f / 1024.f);
    float vv = 0.f;
#pragma unroll
    for (int i = 0; i < 4; i++) { float d = x[i] - mu; vv += d * d; }
    __syncthreads();
    vv = block_reduce_sum_256(vv, sbuf);
    float r = rsqrtf(vv * (1.f / 1024.f) + 1e-5f);
    float* po = out + row * 1024;
#pragma unroll
    for (int i = 0; i < 4; i++) {
        int idx = t + i * 256;
        po[idx] = (x[i] - mu) * r * g[idx] + beta[idx];
    }
}

// ---------------------------------------------------------------------------
extern "C" void kernel_launch(void* const* d_in, const int* in_sizes, int n_in,
                              void* d_out, int out_size)
{
    const float* Q     = (const float*)d_in[0];
    const float* K     = (const float*)d_in[1];
    const int*   mask  = (const int*)d_in[2];
    const float* Wq    = (const float*)d_in[3];
    const float* bq    = (const float*)d_in[4];
    const float* Wk    = (const float*)d_in[5];
    const float* bk    = (const float*)d_in[6];
    const float* Wv    = (const float*)d_in[7];
    const float* bv    = (const float*)d_in[8];
    const float* Wp    = (const float*)d_in[9];
    const float* bp    = (const float*)d_in[10];
    const float* g0    = (const float*)d_in[11];
    const float* beta0 = (const float*)d_in[12];
    const float* g1    = (const float*)d_in[13];
    const float* beta1 = (const float*)d_in[14];
    float* out = (float*)d_out;

    float *q, *v, *ctx, *o1, *h;
    cudaGetSymbolAddress((void**)&q,   g_q);
    cudaGetSymbolAddress((void**)&v,   g_v);
    cudaGetSymbolAddress((void**)&ctx, g_ctx);
    cudaGetSymbolAddress((void**)&o1,  g_o1);
    cudaGetSymbolAddress((void**)&h,   g_h);

    __nv_bfloat16 *iqh, *iql, *ikh, *ikl, *pqh, *pql, *pkh, *pkl, *vth, *vtl, *o1h, *o1l;
    cudaGetSymbolAddress((void**)&iqh, g_iqh); cudaGetSymbolAddress((void**)&iql, g_iql);
    cudaGetSymbolAddress((void**)&ikh, g_ikh); cudaGetSymbolAddress((void**)&ikl, g_ikl);
    cudaGetSymbolAddress((void**)&pqh, g_pqh); cudaGetSymbolAddress((void**)&pql, g_pql);
    cudaGetSymbolAddress((void**)&pkh, g_pkh); cudaGetSymbolAddress((void**)&pkl, g_pkl);
    cudaGetSymbolAddress((void**)&vth, g_vth); cudaGetSymbolAddress((void**)&vtl, g_vtl);
    cudaGetSymbolAddress((void**)&o1h, g_o1h); cudaGetSymbolAddress((void**)&o1l, g_o1l);
    __nv_bfloat16 *wqh, *wql, *wkh, *wkl, *wvh, *wvl, *wph, *wpl;
    cudaGetSymbolAddress((void**)&wqh, g_wqh); cudaGetSymbolAddress((void**)&wql, g_wql);
    cudaGetSymbolAddress((void**)&wkh, g_wkh); cudaGetSymbolAddress((void**)&wkl, g_wkl);
    cudaGetSymbolAddress((void**)&wvh, g_wvh); cudaGetSymbolAddress((void**)&wvl, g_wvl);
    cudaGetSymbolAddress((void**)&wph, g_wph); cudaGetSymbolAddress((void**)&wpl, g_wpl);

    cudaFuncSetAttribute(tgemm_kernel, cudaFuncAttributeMaxDynamicSharedMemorySize, GEMM_SMEM);
    cudaFuncSetAttribute(attn_mma_kernel, cudaFuncAttributeMaxDynamicSharedMemorySize, ATT_SMEM);

    const int n4 = MTOT * D_ / 4;
    dim3 cblk(256), cgrid(n4 / 256);

    conv_hilo_kernel<<<cgrid, cblk>>>((const float4*)Q, (__nv_bfloat162*)iqh, (__nv_bfloat162*)iql, n4);
    conv_hilo_kernel<<<cgrid, cblk>>>((const float4*)K, (__nv_bfloat162*)ikh, (__nv_bfloat162*)ikl, n4);

    dim3 wgrid(32, 32), wblk(32, 8);
    conv_w_kernel<<<wgrid, wblk>>>(Wq, wqh, wql);
    conv_w_kernel<<<wgrid, wblk>>>(Wk, wkh, wkl);
    conv_w_kernel<<<wgrid, wblk>>>(Wv, wvh, wvl);
    conv_w_kernel<<<wgrid, wblk>>>(Wp, wph, wpl);

    dim3 ggrid(D_ / TN, MTOT / TM);   // (8, 64)
    tgemm_kernel<<<ggrid, 256, GEMM_SMEM>>>(iqh, iql, wqh, wql, bq, q, pqh, pql);
    tgemm_kernel<<<ggrid, 256, GEMM_SMEM>>>(ikh, ikl, wkh, wkl, bk, nullptr, pkh, pkl);
    tgemm_kernel<<<ggrid, 256, GEMM_SMEM>>>(ikh, ikl, wvh, wvl, bv, v, nullptr, nullptr);

    dim3 vtgrid(32, 32, 8);
    vtrans_kernel<<<vtgrid, wblk>>>(v, vth, vtl);

    dim3 agrid(SQ_ / 128, H_, B_);
    attn_mma_kernel<<<agrid, 256, ATT_SMEM>>>(pqh, pql, pkh, pkl, vth, vtl, mask, ctx);

    ln_add_kernel<<<MTOT, 256>>>(q, ctx, g0, beta0, o1, o1h, o1l);

    tgemm_kernel<<<ggrid, 256, GEMM_SMEM>>>(o1h, o1l, wph, wpl, bp, h, nullptr, nullptr);

    ln_gelu_kernel<<<MTOT, 256>>>(o1, h, g1, beta1, out);
}

// round 5
// speedup vs baseline: 7.5924x; 2.1761x over previous
#include <cuda_runtime.h>
#include <cuda_fp16.h>
#include <math.h>
#include <stdint.h>

#define B_ 8
#define SQ_ 1024
#define SKV_ 1024
#define D_ 1024
#define H_ 16
#define HD_ 64
#define MTOT (B_*SQ_)   // 8192

// ---------------- scratch (device globals; allocation-free rule) -----------
__device__ float g_q  [MTOT*D_];
__device__ float g_v  [MTOT*D_];
__device__ float g_ctx[MTOT*D_];
__device__ float g_o1 [MTOT*D_];
__device__ float g_h  [MTOT*D_];

__device__ __half g_iq[MTOT*D_];            // Q input fp16
__device__ __half g_ik[MTOT*D_];            // K input fp16
__device__ __half g_pq[MTOT*D_];            // projected q fp16 (pre-scaled by 1/8)
__device__ __half g_pk[MTOT*D_];            // projected k fp16
__device__ __half g_vt[MTOT*D_];            // V^T fp16 [B,H,64,Skv]
__device__ __half g_o1f[MTOT*D_];           // o1 fp16
__device__ __half g_wq[D_*D_], g_wk[D_*D_], g_wv[D_*D_], g_wp[D_*D_]; // W^T fp16

// ---------------- helpers ----------------------------------------------------
__device__ __forceinline__ uint32_t smem_to_u32(const void* p) {
    uint32_t a;
    asm("{ .reg .u64 t; cvta.to.shared.u64 t, %1; cvt.u32.u64 %0, t; }" : "=r"(a) : "l"(p));
    return a;
}
#define CP_ASYNC16(dst_u32, gptr) \
    asm volatile("cp.async.cg.shared.global [%0], [%1], 16;" :: "r"(dst_u32), "l"(gptr) : "memory")
#define CP_COMMIT() asm volatile("cp.async.commit_group;" ::: "memory")
#define CP_WAIT1()  asm volatile("cp.async.wait_group 1;" ::: "memory")
#define CP_WAIT0()  asm volatile("cp.async.wait_group 0;" ::: "memory")

#define LDSM_X4(r0,r1,r2,r3,addr) \
    asm volatile("ldmatrix.sync.aligned.m8n8.x4.shared.b16 {%0,%1,%2,%3}, [%4];" \
        : "=r"(r0),"=r"(r1),"=r"(r2),"=r"(r3) : "r"(addr))

#define MMA_F16(c, a, b0v, b1v) \
    asm volatile("mma.sync.aligned.m16n8k16.row.col.f32.f16.f16.f32 " \
        "{%0,%1,%2,%3}, {%4,%5,%6,%7}, {%8,%9}, {%0,%1,%2,%3};" \
        : "+f"((c)[0]),"+f"((c)[1]),"+f"((c)[2]),"+f"((c)[3]) \
        : "r"((a)[0]),"r"((a)[1]),"r"((a)[2]),"r"((a)[3]), "r"(b0v),"r"(b1v))

__device__ __forceinline__ uint32_t pack_h2(float x, float y) {
    __half2 t = __floats2half2_rn(x, y);
    return *reinterpret_cast<uint32_t*>(&t);
}

// ---------------------------------------------------------------------------
// GEMM: C = A@W + bias. A fp16 [M][K]; W transposed fp16 [N][K].
// Tile 128x128, K-chunk 64, cp.async double buffer, single fp16 mma.sync.
// Outputs: optional fp32 Cf, optional fp16 Ch scaled by oscale.
// ---------------------------------------------------------------------------
#define TM 128
#define TN 128
#define TK 64
#define OFF_A 0
#define OFF_B 16384
#define STAGE_BYTES 32768
#define SMEM_BUF0 1024
#define GEMM_SMEM (SMEM_BUF0 + 2*STAGE_BYTES)   // 66560

__global__ void __launch_bounds__(256, 2) tgemm_kernel(
    const __half* __restrict__ A, const __half* __restrict__ W,
    const float* __restrict__ bias, float* __restrict__ Cf,
    __half* __restrict__ Ch, float oscale)
{
    extern __shared__ char smem[];
    uint32_t sb = smem_to_u32(smem);
    int tid = threadIdx.x, wid = tid >> 5, lid = tid & 31;
    int row0 = blockIdx.y * TM;
    int col0 = blockIdx.x * TN;

    auto load_chunk = [&](int buf, int kc) {
        uint32_t base = sb + SMEM_BUF0 + buf * STAGE_BYTES;
        int k0 = kc * TK;
#pragma unroll
        for (int i = 0; i < 4; i++) {
            int u = tid + i * 256;
            int r = u >> 3, c = u & 7;
            uint32_t byte = (uint32_t)(r * 128 + c * 16);
            uint32_t sw = byte ^ ((byte >> 3) & 0x70);
            CP_ASYNC16(base + OFF_A + sw, A + (size_t)(row0 + r) * D_ + k0 + c * 8);
            CP_ASYNC16(base + OFF_B + sw, W + (size_t)(col0 + r) * D_ + k0 + c * 8);
        }
    };

    int wm = wid & 3;
    int wn = wid >> 2;

    float acc[2][8][4];
#pragma unroll
    for (int i = 0; i < 2; i++)
#pragma unroll
        for (int j = 0; j < 8; j++)
#pragma unroll
            for (int e = 0; e < 4; e++) acc[i][j][e] = 0.f;

    load_chunk(0, 0); CP_COMMIT();
    for (int kc = 0; kc < 16; kc++) {
        int buf = kc & 1;
        if (kc + 1 < 16) { load_chunk(buf ^ 1, kc + 1); CP_COMMIT(); CP_WAIT1(); }
        else             { CP_WAIT0(); }
        __syncthreads();

        uint32_t base = sb + SMEM_BUF0 + buf * STAGE_BYTES;
        uint32_t sa = base + OFF_A, sw_ = base + OFF_B;

#pragma unroll
        for (int ks = 0; ks < 4; ks++) {
            uint32_t af[2][4];
#pragma unroll
            for (int mi = 0; mi < 2; mi++) {
                int rowa = wm * 32 + mi * 16 + (lid & 15);
                uint32_t byte = (uint32_t)(rowa * 128 + ks * 32 + ((lid >> 4) << 4));
                uint32_t sw = byte ^ ((byte >> 3) & 0x70);
                LDSM_X4(af[mi][0], af[mi][1], af[mi][2], af[mi][3], sa + sw);
            }
#pragma unroll
            for (int nj = 0; nj < 4; nj++) {
                int rowb = wn * 64 + nj * 16 + (lid & 7) + ((lid >> 4) << 3);
                uint32_t byte = (uint32_t)(rowb * 128 + ks * 32 + (((lid >> 3) & 1) << 4));
                uint32_t sw = byte ^ ((byte >> 3) & 0x70);
                uint32_t b0, b1, b2, b3;
                LDSM_X4(b0, b1, b2, b3, sw_ + sw);
#pragma unroll
                for (int mi = 0; mi < 2; mi++) {
                    MMA_F16(acc[mi][2*nj],   af[mi], b0, b1);
                    MMA_F16(acc[mi][2*nj+1], af[mi], b2, b3);
                }
            }
        }
        __syncthreads();
    }

#pragma unroll
    for (int mi = 0; mi < 2; mi++) {
#pragma unroll
        for (int nj = 0; nj < 8; nj++) {
            int m = row0 + wm * 32 + mi * 16 + (lid >> 2);
            int n = col0 + wn * 64 + nj * 8 + (lid & 3) * 2;
            float bn0 = __ldg(bias + n), bn1 = __ldg(bias + n + 1);
            float v00 = acc[mi][nj][0] + bn0, v01 = acc[mi][nj][1] + bn1;
            float v10 = acc[mi][nj][2] + bn0, v11 = acc[mi][nj][3] + bn1;
            if (Cf) {
                *(float2*)(Cf + (size_t)m * D_ + n) = make_float2(v00, v01);
                *(float2*)(Cf + (size_t)(m + 8) * D_ + n) = make_float2(v10, v11);
            }
            if (Ch) {
                *(uint32_t*)(Ch + (size_t)m * D_ + n) = pack_h2(v00 * oscale, v01 * oscale);
                *(uint32_t*)(Ch + (size_t)(m + 8) * D_ + n) = pack_h2(v10 * oscale, v11 * oscale);
            }
        }
    }
}

// ---------------------------------------------------------------------------
// Tensor-core flash attention (fp16 single-pass). CTA = 128 queries x (b,h).
// q pre-scaled by 1/8 so S = q K^T needs no extra scale.
// ---------------------------------------------------------------------------
#define AOFF_Q 0
#define AOFF_STAGE 16384
#define ASTAGE_BYTES 16384
#define ATT_SMEM (16384 + 2*16384 + 512)   // 49664

__global__ void __launch_bounds__(256, 2) attn_mma_kernel(
    const __half* __restrict__ pq, const __half* __restrict__ pk,
    const __half* __restrict__ vt, const int* __restrict__ mask,
    float* __restrict__ ctxout)
{
    extern __shared__ char smem[];
    uint32_t sb = smem_to_u32(smem);
    int* msm = (int*)(smem + AOFF_STAGE + 2 * ASTAGE_BYTES);   // [2][64]

    int b = blockIdx.z, h = blockIdx.y;
    int q0 = blockIdx.x * 128;
    int tid = threadIdx.x, wid = tid >> 5, lid = tid & 31;

    // Q tile (128 x 64 fp16) via cp.async
#pragma unroll
    for (int i = 0; i < 4; i++) {
        int u = tid + i * 256;
        int r = u >> 3, c = u & 7;
        uint32_t byte = (uint32_t)(r * 128 + c * 16);
        uint32_t sw = byte ^ ((byte >> 3) & 0x70);
        CP_ASYNC16(sb + AOFF_Q + sw, pq + (size_t)(b * SQ_ + q0 + r) * D_ + h * HD_ + c * 8);
    }

    auto load_stage = [&](int buf, int kt) {
        uint32_t base = sb + AOFF_STAGE + buf * ASTAGE_BYTES;
        int kv0 = kt * 64;
#pragma unroll
        for (int i = 0; i < 2; i++) {
            int u = tid + i * 256;
            int r = u >> 3, c = u & 7;
            uint32_t byte = (uint32_t)(r * 128 + c * 16);
            uint32_t sw = byte ^ ((byte >> 3) & 0x70);
            CP_ASYNC16(base + 0    + sw, pk + (size_t)(b * SKV_ + kv0 + r) * D_ + h * HD_ + c * 8);
            CP_ASYNC16(base + 8192 + sw, vt + ((size_t)(b * H_ + h) * HD_ + r) * SKV_ + kv0 + c * 8);
        }
        if (tid < 64) msm[buf * 64 + tid] = mask[b * SKV_ + kv0 + tid];
    };

    load_stage(0, 0);
    CP_COMMIT();

    uint32_t qf[4][4];
    float ctx[8][4];
#pragma unroll
    for (int t = 0; t < 8; t++)
#pragma unroll
        for (int e = 0; e < 4; e++) ctx[t][e] = 0.f;
    float rm0 = -1e30f, rm1 = -1e30f, rl0 = 0.f, rl1 = 0.f;

    for (int kt = 0; kt < 16; kt++) {
        int buf = kt & 1;
        __syncthreads();
        if (kt + 1 < 16) { load_stage(buf ^ 1, kt + 1); CP_COMMIT(); CP_WAIT1(); }
        else             { CP_WAIT0(); }
        __syncthreads();

        if (kt == 0) {
#pragma unroll
            for (int ks = 0; ks < 4; ks++) {
                int rowa = wid * 16 + (lid & 15);
                uint32_t byte = (uint32_t)(rowa * 128 + ks * 32 + ((lid >> 4) << 4));
                uint32_t sw = byte ^ ((byte >> 3) & 0x70);
                LDSM_X4(qf[ks][0], qf[ks][1], qf[ks][2], qf[ks][3], sb + AOFF_Q + sw);
            }
        }

        uint32_t base = sb + AOFF_STAGE + buf * ASTAGE_BYTES;
        // ---- S = q K^T (q pre-scaled) ----
        float sacc[8][4];
#pragma unroll
        for (int t = 0; t < 8; t++)
#pragma unroll
            for (int e = 0; e < 4; e++) sacc[t][e] = 0.f;

#pragma unroll
        for (int ks = 0; ks < 4; ks++) {
#pragma unroll
            for (int nj = 0; nj < 4; nj++) {
                int rowb = nj * 16 + (lid & 7) + ((lid >> 4) << 3);
                uint32_t byte = (uint32_t)(rowb * 128 + ks * 32 + (((lid >> 3) & 1) << 4));
                uint32_t sw = byte ^ ((byte >> 3) & 0x70);
                uint32_t k0, k1, k2, k3;
                LDSM_X4(k0, k1, k2, k3, base + 0 + sw);
                MMA_F16(sacc[2*nj],   qf[ks], k0, k1);
                MMA_F16(sacc[2*nj+1], qf[ks], k2, k3);
            }
        }

        // ---- mask + online softmax ----
        const int* mrow = msm + buf * 64;
        float mx0 = -1e30f, mx1 = -1e30f;
#pragma unroll
        for (int t = 0; t < 8; t++) {
            int cb = t * 8 + (lid & 3) * 2;
            bool k0 = mrow[cb] != 0, k1 = mrow[cb + 1] != 0;
            float s00 = k0 ? sacc[t][0] : -1e30f;
            float s01 = k1 ? sacc[t][1] : -1e30f;
            float s10 = k0 ? sacc[t][2] : -1e30f;
            float s11 = k1 ? sacc[t][3] : -1e30f;
            sacc[t][0] = s00; sacc[t][1] = s01; sacc[t][2] = s10; sacc[t][3] = s11;
            mx0 = fmaxf(mx0, fmaxf(s00, s01));
            mx1 = fmaxf(mx1, fmaxf(s10, s11));
        }
        mx0 = fmaxf(mx0, __shfl_xor_sync(0xffffffffu, mx0, 1));
        mx0 = fmaxf(mx0, __shfl_xor_sync(0xffffffffu, mx0, 2));
        mx1 = fmaxf(mx1, __shfl_xor_sync(0xffffffffu, mx1, 1));
        mx1 = fmaxf(mx1, __shfl_xor_sync(0xffffffffu, mx1, 2));

        float mn0 = fmaxf(rm0, mx0), mn1 = fmaxf(rm1, mx1);
        float sc0 = __expf(rm0 - mn0), sc1 = __expf(rm1 - mn1);
        rm0 = mn0; rm1 = mn1;
        float ps0 = 0.f, ps1 = 0.f;
#pragma unroll
        for (int t = 0; t < 8; t++) {
            float p00 = __expf(sacc[t][0] - mn0);
            float p01 = __expf(sacc[t][1] - mn0);
            float p10 = __expf(sacc[t][2] - mn1);
            float p11 = __expf(sacc[t][3] - mn1);
            sacc[t][0] = p00; sacc[t][1] = p01; sacc[t][2] = p10; sacc[t][3] = p11;
            ps0 += p00 + p01;
            ps1 += p10 + p11;
            ctx[t][0] *= sc0; ctx[t][1] *= sc0;
            ctx[t][2] *= sc1; ctx[t][3] *= sc1;
        }
        ps0 += __shfl_xor_sync(0xffffffffu, ps0, 1);
        ps0 += __shfl_xor_sync(0xffffffffu, ps0, 2);
        ps1 += __shfl_xor_sync(0xffffffffu, ps1, 1);
        ps1 += __shfl_xor_sync(0xffffffffu, ps1, 2);
        rl0 = rl0 * sc0 + ps0;
        rl1 = rl1 * sc1 + ps1;

        // ---- P fragments (fp16) ----
        uint32_t pf[4][4];
#pragma unroll
        for (int j = 0; j < 4; j++) {
            pf[j][0] = pack_h2(sacc[2*j][0],   sacc[2*j][1]);
            pf[j][1] = pack_h2(sacc[2*j][2],   sacc[2*j][3]);
            pf[j][2] = pack_h2(sacc[2*j+1][0], sacc[2*j+1][1]);
            pf[j][3] = pack_h2(sacc[2*j+1][2], sacc[2*j+1][3]);
        }

        // ---- ctx += P V ----
#pragma unroll
        for (int ks = 0; ks < 4; ks++) {
#pragma unroll
            for (int nj = 0; nj < 4; nj++) {
                int rowb = nj * 16 + (lid & 7) + ((lid >> 4) << 3);
                uint32_t byte = (uint32_t)(rowb * 128 + ks * 32 + (((lid >> 3) & 1) << 4));
                uint32_t sw = byte ^ ((byte >> 3) & 0x70);
                uint32_t v0, v1, v2, v3;
                LDSM_X4(v0, v1, v2, v3, base + 8192 + sw);
                MMA_F16(ctx[2*nj],   pf[ks], v0, v1);
                MMA_F16(ctx[2*nj+1], pf[ks], v2, v3);
            }
        }
    }

    // ---- epilogue ----
    float inv0 = 1.f / rl0, inv1 = 1.f / rl1;
    int row = q0 + wid * 16 + (lid >> 2);
#pragma unroll
    for (int t = 0; t < 8; t++) {
        int col = h * HD_ + t * 8 + (lid & 3) * 2;
        *(float2*)(ctxout + (size_t)(b * SQ_ + row) * D_ + col) =
            make_float2(ctx[t][0] * inv0, ctx[t][1] * inv0);
        *(float2*)(ctxout + (size_t)(b * SQ_ + row + 8) * D_ + col) =
            make_float2(ctx[t][2] * inv1, ctx[t][3] * inv1);
    }
}

// ---------------------------------------------------------------------------
// fp32 -> fp16 (elementwise)
// ---------------------------------------------------------------------------
__global__ void __launch_bounds__(256) conv_h_kernel(
    const float4* __restrict__ src, __half2* __restrict__ dst, int n4)
{
    int i = blockIdx.x * 256 + threadIdx.x;
    if (i >= n4) return;
    float4 v = src[i];
    dst[2 * i]     = __floats2half2_rn(v.x, v.y);
    dst[2 * i + 1] = __floats2half2_rn(v.z, v.w);
}

// ---------------------------------------------------------------------------
// Weight transpose + fp16: W[K][N] -> Wt[N][K]
// ---------------------------------------------------------------------------
__global__ void __launch_bounds__(256) conv_w_kernel(
    const float* __restrict__ W, __half* __restrict__ t16)
{
    __shared__ float t[32][33];
    int n0 = blockIdx.x * 32, k0 = blockIdx.y * 32;
    int x = threadIdx.x, y = threadIdx.y;
#pragma unroll
    for (int i = y; i < 32; i += 8)
        t[i][x] = W[(size_t)(k0 + i) * D_ + n0 + x];
    __syncthreads();
#pragma unroll
    for (int r = y; r < 32; r += 8)
        t16[(size_t)(n0 + r) * D_ + k0 + x] = __float2half(t[x][r]);
}

// ---------------------------------------------------------------------------
// V transpose + fp16: v fp32 [B,S,D] -> vt fp16 [B,H,64,Skv]
// ---------------------------------------------------------------------------
__global__ void __launch_bounds__(256) vtrans_kernel(
    const float* __restrict__ v, __half* __restrict__ vt)
{
    __shared__ float t[32][33];
    int b = blockIdx.z;
    int hh = blockIdx.y;
    int h = hh >> 1, hd0 = (hh & 1) * 32;
    int s0 = blockIdx.x * 32;
    int x = threadIdx.x, y = threadIdx.y;
#pragma unroll
    for (int i = y; i < 32; i += 8)
        t[i][x] = v[(size_t)(b * SQ_ + s0 + i) * D_ + h * HD_ + hd0 + x];
    __syncthreads();
#pragma unroll
    for (int r = y; r < 32; r += 8)
        vt[((size_t)(b * H_ + h) * HD_ + hd0 + r) * SKV_ + s0 + x] = __float2half(t[x][r]);
}

// ---------------------------------------------------------------------------
// LayerNorm kernels
// ---------------------------------------------------------------------------
__device__ __forceinline__ float block_reduce_sum_256(float val, float* sbuf)
{
    int lane = threadIdx.x & 31, w = threadIdx.x >> 5;
#pragma unroll
    for (int o = 16; o; o >>= 1) val += __shfl_xor_sync(0xffffffff, val, o);
    if (lane == 0) sbuf[w] = val;
    __syncthreads();
    float r = (threadIdx.x < 8) ? sbuf[threadIdx.x] : 0.f;
    if (w == 0) {
#pragma unroll
        for (int o = 4; o; o >>= 1) r += __shfl_xor_sync(0xffffffff, r, o);
        if (lane == 0) sbuf[0] = r;
    }
    __syncthreads();
    return sbuf[0];
}

// out = LN(a + b) fp32; also fp16 copy
__global__ void __launch_bounds__(256) ln_add_kernel(
    const float* __restrict__ a, const float* __restrict__ bsrc,
    const float* __restrict__ g, const float* __restrict__ beta,
    float* __restrict__ out, __half* __restrict__ outh)
{
    __shared__ float sbuf[8];
    size_t row = blockIdx.x;
    int t = threadIdx.x;
    const float* pa = a + row * 1024;
    const float* pb = bsrc + row * 1024;
    float x[4];
    float s = 0.f;
#pragma unroll
    for (int i = 0; i < 4; i++) { int idx = t + i * 256; x[i] = pa[idx] + pb[idx]; s += x[i]; }
    s = block_reduce_sum_256(s, sbuf);
    float mu = s * (1.f / 1024.f);
    float vv = 0.f;
#pragma unroll
    for (int i = 0; i < 4; i++) { float d = x[i] - mu; vv += d * d; }
    __syncthreads();
    vv = block_reduce_sum_256(vv, sbuf);
    float r = rsqrtf(vv * (1.f / 1024.f) + 1e-5f);
#pragma unroll
    for (int i = 0; i < 4; i++) {
        int idx = t + i * 256;
        float y = (x[i] - mu) * r * g[idx] + beta[idx];
        out[row * 1024 + idx] = y;
        outh[row * 1024 + idx] = __float2half(y);
    }
}

__global__ void __launch_bounds__(256) ln_gelu_kernel(
    const float* __restrict__ a, const float* __restrict__ bsrc,
    const float* __restrict__ g, const float* __restrict__ beta,
    float* __restrict__ out)
{
    __shared__ float sbuf[8];
    size_t row = blockIdx.x;
    int t = threadIdx.x;
    const float* pa = a + row * 1024;
    const float* pb = bsrc + row * 1024;
    float x[4];
    float s = 0.f;
#pragma unroll
    for (int i = 0; i < 4; i++) {
        int idx = t + i * 256;
        float hv = pb[idx];
        float ge = 0.5f * hv * (1.f + erff(hv * 0.70710678118654752f));
        x[i] = pa[idx] + ge;
        s += x[i];
    }
    s = block_reduce_sum_256(s, sbuf);
    float mu = s * (1.f / 1024.f);
    float vv = 0.f;
#pragma unroll
    for (int i = 0; i < 4; i++) { float d = x[i] - mu; vv += d * d; }
    __syncthreads();
    vv = block_reduce_sum_256(vv, sbuf);
    float r = rsqrtf(vv * (1.f / 1024.f) + 1e-5f);
    float* po = out + row * 1024;
#pragma unroll
    for (int i = 0; i < 4; i++) {
        int idx = t + i * 256;
        po[idx] = (x[i] - mu) * r * g[idx] + beta[idx];
    }
}

// ---------------------------------------------------------------------------
extern "C" void kernel_launch(void* const* d_in, const int* in_sizes, int n_in,
                              void* d_out, int out_size)
{
    const float* Q     = (const float*)d_in[0];
    const float* K     = (const float*)d_in[1];
    const int*   mask  = (const int*)d_in[2];
    const float* Wq    = (const float*)d_in[3];
    const float* bq    = (const float*)d_in[4];
    const float* Wk    = (const float*)d_in[5];
    const float* bk    = (const float*)d_in[6];
    const float* Wv    = (const float*)d_in[7];
    const float* bv    = (const float*)d_in[8];
    const float* Wp    = (const float*)d_in[9];
    const float* bp    = (const float*)d_in[10];
    const float* g0    = (const float*)d_in[11];
    const float* beta0 = (const float*)d_in[12];
    const float* g1    = (const float*)d_in[13];
    const float* beta1 = (const float*)d_in[14];
    float* out = (float*)d_out;

    float *q, *v, *ctx, *o1, *h;
    cudaGetSymbolAddress((void**)&q,   g_q);
    cudaGetSymbolAddress((void**)&v,   g_v);
    cudaGetSymbolAddress((void**)&ctx, g_ctx);
    cudaGetSymbolAddress((void**)&o1,  g_o1);
    cudaGetSymbolAddress((void**)&h,   g_h);

    __half *iq, *ik, *pq, *pk, *vt, *o1f, *wq, *wk, *wv, *wp;
    cudaGetSymbolAddress((void**)&iq,  g_iq);
    cudaGetSymbolAddress((void**)&ik,  g_ik);
    cudaGetSymbolAddress((void**)&pq,  g_pq);
    cudaGetSymbolAddress((void**)&pk,  g_pk);
    cudaGetSymbolAddress((void**)&vt,  g_vt);
    cudaGetSymbolAddress((void**)&o1f, g_o1f);
    cudaGetSymbolAddress((void**)&wq,  g_wq);
    cudaGetSymbolAddress((void**)&wk,  g_wk);
    cudaGetSymbolAddress((void**)&wv,  g_wv);
    cudaGetSymbolAddress((void**)&wp,  g_wp);

    cudaFuncSetAttribute(tgemm_kernel, cudaFuncAttributeMaxDynamicSharedMemorySize, GEMM_SMEM);
    cudaFuncSetAttribute(attn_mma_kernel, cudaFuncAttributeMaxDynamicSharedMemorySize, ATT_SMEM);

    const int n4 = MTOT * D_ / 4;
    dim3 cblk(256), cgrid(n4 / 256);

    conv_h_kernel<<<cgrid, cblk>>>((const float4*)Q, (__half2*)iq, n4);
    conv_h_kernel<<<cgrid, cblk>>>((const float4*)K, (__half2*)ik, n4);

    dim3 wgrid(32, 32), wblk(32, 8);
    conv_w_kernel<<<wgrid, wblk>>>(Wq, wq);
    conv_w_kernel<<<wgrid, wblk>>>(Wk, wk);
    conv_w_kernel<<<wgrid, wblk>>>(Wv, wv);
    conv_w_kernel<<<wgrid, wblk>>>(Wp, wp);

    dim3 ggrid(D_ / TN, MTOT / TM);   // (8, 64)
    tgemm_kernel<<<ggrid, 256, GEMM_SMEM>>>(iq, wq, bq, q, pq, 0.125f);  // q: fp32 + pre-scaled fp16
    tgemm_kernel<<<ggrid, 256, GEMM_SMEM>>>(ik, wk, bk, nullptr, pk, 1.0f);
    tgemm_kernel<<<ggrid, 256, GEMM_SMEM>>>(ik, wv, bv, v, nullptr, 1.0f);

    dim3 vtgrid(32, 32, 8);
    vtrans_kernel<<<vtgrid, wblk>>>(v, vt);

    dim3 agrid(SQ_ / 128, H_, B_);
    attn_mma_kernel<<<agrid, 256, ATT_SMEM>>>(pq, pk, vt, mask, ctx);

    ln_add_kernel<<<MTOT, 256>>>(q, ctx, g0, beta0, o1, o1f);

    tgemm_kernel<<<ggrid, 256, GEMM_SMEM>>>(o1f, wp, bp, h, nullptr, 1.0f);

    ln_gelu_kernel<<<MTOT, 256>>>(o1, h, g1, beta1, out);
}

// round 6
// speedup vs baseline: 7.9204x; 1.0432x over previous
#include <cuda_runtime.h>
#include <cuda_fp16.h>
#include <math.h>
#include <stdint.h>

#define B_ 8
#define SQ_ 1024
#define SKV_ 1024
#define D_ 1024
#define H_ 16
#define HD_ 64
#define MTOT (B_*SQ_)   // 8192

// ---------------- scratch (device globals; allocation-free rule) -----------
__device__ float g_q  [MTOT*D_];
__device__ float g_v  [MTOT*D_];
__device__ float g_ctx[MTOT*D_];
__device__ float g_o1 [MTOT*D_];
__device__ float g_h  [MTOT*D_];

__device__ __half g_iq[MTOT*D_];            // Q input fp16
__device__ __half g_ik[MTOT*D_];            // K input fp16
__device__ __half g_pq[MTOT*D_];            // projected q fp16 (pre-scaled by 1/8)
__device__ __half g_pk[MTOT*D_];            // projected k fp16
__device__ __half g_vt[MTOT*D_];            // V^T fp16 [B,H,64,Skv]
__device__ __half g_o1f[MTOT*D_];           // o1 fp16
__device__ __half g_wq[D_*D_], g_wk[D_*D_], g_wv[D_*D_], g_wp[D_*D_]; // W^T fp16

// ---------------- helpers ----------------------------------------------------
__device__ __forceinline__ uint32_t smem_to_u32(const void* p) {
    uint32_t a;
    asm("{ .reg .u64 t; cvta.to.shared.u64 t, %1; cvt.u32.u64 %0, t; }" : "=r"(a) : "l"(p));
    return a;
}
#define CP_ASYNC16(dst_u32, gptr) \
    asm volatile("cp.async.cg.shared.global [%0], [%1], 16;" :: "r"(dst_u32), "l"(gptr) : "memory")
#define CP_COMMIT() asm volatile("cp.async.commit_group;" ::: "memory")
#define CP_WAIT1()  asm volatile("cp.async.wait_group 1;" ::: "memory")
#define CP_WAIT0()  asm volatile("cp.async.wait_group 0;" ::: "memory")

#define LDSM_X4(r0,r1,r2,r3,addr) \
    asm volatile("ldmatrix.sync.aligned.m8n8.x4.shared.b16 {%0,%1,%2,%3}, [%4];" \
        : "=r"(r0),"=r"(r1),"=r"(r2),"=r"(r3) : "r"(addr))

#define MMA_F16(c, a, b0v, b1v) \
    asm volatile("mma.sync.aligned.m16n8k16.row.col.f32.f16.f16.f32 " \
        "{%0,%1,%2,%3}, {%4,%5,%6,%7}, {%8,%9}, {%0,%1,%2,%3};" \
        : "+f"((c)[0]),"+f"((c)[1]),"+f"((c)[2]),"+f"((c)[3]) \
        : "r"((a)[0]),"r"((a)[1]),"r"((a)[2]),"r"((a)[3]), "r"(b0v),"r"(b1v))

__device__ __forceinline__ uint32_t pack_h2(float x, float y) {
    __half2 t = __floats2half2_rn(x, y);
    return *reinterpret_cast<uint32_t*>(&t);
}

// ---------------------------------------------------------------------------
// GEMM: C = A@W + bias. A fp16 [M][K]; W transposed fp16 [N][K].
// CTA tile 128x128, 4 warps, warp tile 64x64 (LDSM:MMA = 1:4).
// K-chunk 64, cp.async double buffer.
// ---------------------------------------------------------------------------
#define TM 128
#define TN 128
#define TK 64
#define OFF_A 0
#define OFF_B 16384
#define STAGE_BYTES 32768
#define SMEM_BUF0 1024
#define GEMM_SMEM (SMEM_BUF0 + 2*STAGE_BYTES)   // 66560

__global__ void __launch_bounds__(128, 2) tgemm_kernel(
    const __half* __restrict__ A, const __half* __restrict__ W,
    const float* __restrict__ bias, float* __restrict__ Cf,
    __half* __restrict__ Ch, float oscale)
{
    extern __shared__ char smem[];
    uint32_t sb = smem_to_u32(smem);
    int tid = threadIdx.x, wid = tid >> 5, lid = tid & 31;
    int row0 = blockIdx.y * TM;
    int col0 = blockIdx.x * TN;

    auto load_chunk = [&](int buf, int kc) {
        uint32_t base = sb + SMEM_BUF0 + buf * STAGE_BYTES;
        int k0 = kc * TK;
#pragma unroll
        for (int i = 0; i < 8; i++) {
            int u = tid + i * 128;
            int r = u >> 3, c = u & 7;
            uint32_t byte = (uint32_t)(r * 128 + c * 16);
            uint32_t sw = byte ^ ((byte >> 3) & 0x70);
            CP_ASYNC16(base + OFF_A + sw, A + (size_t)(row0 + r) * D_ + k0 + c * 8);
            CP_ASYNC16(base + OFF_B + sw, W + (size_t)(col0 + r) * D_ + k0 + c * 8);
        }
    };

    int wm = wid & 1;      // 2 warps over M: 64 rows each
    int wn = wid >> 1;     // 2 warps over N: 64 cols each

    float acc[4][8][4];
#pragma unroll
    for (int i = 0; i < 4; i++)
#pragma unroll
        for (int j = 0; j < 8; j++)
#pragma unroll
            for (int e = 0; e < 4; e++) acc[i][j][e] = 0.f;

    load_chunk(0, 0); CP_COMMIT();
    for (int kc = 0; kc < 16; kc++) {
        int buf = kc & 1;
        if (kc + 1 < 16) { load_chunk(buf ^ 1, kc + 1); CP_COMMIT(); CP_WAIT1(); }
        else             { CP_WAIT0(); }
        __syncthreads();

        uint32_t base = sb + SMEM_BUF0 + buf * STAGE_BYTES;
        uint32_t sa = base + OFF_A, sw_ = base + OFF_B;

#pragma unroll
        for (int ks = 0; ks < 4; ks++) {
            uint32_t af[4][4];
#pragma unroll
            for (int mi = 0; mi < 4; mi++) {
                int rowa = wm * 64 + mi * 16 + (lid & 15);
                uint32_t byte = (uint32_t)(rowa * 128 + ks * 32 + ((lid >> 4) << 4));
                uint32_t sw = byte ^ ((byte >> 3) & 0x70);
                LDSM_X4(af[mi][0], af[mi][1], af[mi][2], af[mi][3], sa + sw);
            }
#pragma unroll
            for (int nj = 0; nj < 4; nj++) {
                int rowb = wn * 64 + nj * 16 + (lid & 7) + ((lid >> 4) << 3);
                uint32_t byte = (uint32_t)(rowb * 128 + ks * 32 + (((lid >> 3) & 1) << 4));
                uint32_t sw = byte ^ ((byte >> 3) & 0x70);
                uint32_t b0, b1, b2, b3;
                LDSM_X4(b0, b1, b2, b3, sw_ + sw);
#pragma unroll
                for (int mi = 0; mi < 4; mi++) {
                    MMA_F16(acc[mi][2*nj],   af[mi], b0, b1);
                    MMA_F16(acc[mi][2*nj+1], af[mi], b2, b3);
                }
            }
        }
        __syncthreads();
    }

#pragma unroll
    for (int mi = 0; mi < 4; mi++) {
#pragma unroll
        for (int nj = 0; nj < 8; nj++) {
            int m = row0 + wm * 64 + mi * 16 + (lid >> 2);
            int n = col0 + wn * 64 + nj * 8 + (lid & 3) * 2;
            float bn0 = __ldg(bias + n), bn1 = __ldg(bias + n + 1);
            float v00 = acc[mi][nj][0] + bn0, v01 = acc[mi][nj][1] + bn1;
            float v10 = acc[mi][nj][2] + bn0, v11 = acc[mi][nj][3] + bn1;
            if (Cf) {
                *(float2*)(Cf + (size_t)m * D_ + n) = make_float2(v00, v01);
                *(float2*)(Cf + (size_t)(m + 8) * D_ + n) = make_float2(v10, v11);
            }
            if (Ch) {
                *(uint32_t*)(Ch + (size_t)m * D_ + n) = pack_h2(v00 * oscale, v01 * oscale);
                *(uint32_t*)(Ch + (size_t)(m + 8) * D_ + n) = pack_h2(v10 * oscale, v11 * oscale);
            }
        }
    }
}

// ---------------------------------------------------------------------------
// Tensor-core flash attention (fp16 single-pass). CTA = 128 queries x (b,h).
// q pre-scaled by 1/8 so S = q K^T needs no extra scale.
// ---------------------------------------------------------------------------
#define AOFF_Q 0
#define AOFF_STAGE 16384
#define ASTAGE_BYTES 16384
#define ATT_SMEM (16384 + 2*16384 + 512)   // 49664

__global__ void __launch_bounds__(256, 2) attn_mma_kernel(
    const __half* __restrict__ pq, const __half* __restrict__ pk,
    const __half* __restrict__ vt, const int* __restrict__ mask,
    float* __restrict__ ctxout)
{
    extern __shared__ char smem[];
    uint32_t sb = smem_to_u32(smem);
    int* msm = (int*)(smem + AOFF_STAGE + 2 * ASTAGE_BYTES);   // [2][64]

    int b = blockIdx.z, h = blockIdx.y;
    int q0 = blockIdx.x * 128;
    int tid = threadIdx.x, wid = tid >> 5, lid = tid & 31;

#pragma unroll
    for (int i = 0; i < 4; i++) {
        int u = tid + i * 256;
        int r = u >> 3, c = u & 7;
        uint32_t byte = (uint32_t)(r * 128 + c * 16);
        uint32_t sw = byte ^ ((byte >> 3) & 0x70);
        CP_ASYNC16(sb + AOFF_Q + sw, pq + (size_t)(b * SQ_ + q0 + r) * D_ + h * HD_ + c * 8);
    }

    auto load_stage = [&](int buf, int kt) {
        uint32_t base = sb + AOFF_STAGE + buf * ASTAGE_BYTES;
        int kv0 = kt * 64;
#pragma unroll
        for (int i = 0; i < 2; i++) {
            int u = tid + i * 256;
            int r = u >> 3, c = u & 7;
            uint32_t byte = (uint32_t)(r * 128 + c * 16);
            uint32_t sw = byte ^ ((byte >> 3) & 0x70);
            CP_ASYNC16(base + 0    + sw, pk + (size_t)(b * SKV_ + kv0 + r) * D_ + h * HD_ + c * 8);
            CP_ASYNC16(base + 8192 + sw, vt + ((size_t)(b * H_ + h) * HD_ + r) * SKV_ + kv0 + c * 8);
        }
        if (tid < 64) msm[buf * 64 + tid] = mask[b * SKV_ + kv0 + tid];
    };

    load_stage(0, 0);
    CP_COMMIT();

    uint32_t qf[4][4];
    float ctx[8][4];
#pragma unroll
    for (int t = 0; t < 8; t++)
#pragma unroll
        for (int e = 0; e < 4; e++) ctx[t][e] = 0.f;
    float rm0 = -1e30f, rm1 = -1e30f, rl0 = 0.f, rl1 = 0.f;

    for (int kt = 0; kt < 16; kt++) {
        int buf = kt & 1;
        __syncthreads();
        if (kt + 1 < 16) { load_stage(buf ^ 1, kt + 1); CP_COMMIT(); CP_WAIT1(); }
        else             { CP_WAIT0(); }
        __syncthreads();

        if (kt == 0) {
#pragma unroll
            for (int ks = 0; ks < 4; ks++) {
                int rowa = wid * 16 + (lid & 15);
                uint32_t byte = (uint32_t)(rowa * 128 + ks * 32 + ((lid >> 4) << 4));
                uint32_t sw = byte ^ ((byte >> 3) & 0x70);
                LDSM_X4(qf[ks][0], qf[ks][1], qf[ks][2], qf[ks][3], sb + AOFF_Q + sw);
            }
        }

        uint32_t base = sb + AOFF_STAGE + buf * ASTAGE_BYTES;
        float sacc[8][4];
#pragma unroll
        for (int t = 0; t < 8; t++)
#pragma unroll
            for (int e = 0; e < 4; e++) sacc[t][e] = 0.f;

#pragma unroll
        for (int ks = 0; ks < 4; ks++) {
#pragma unroll
            for (int nj = 0; nj < 4; nj++) {
                int rowb = nj * 16 + (lid & 7) + ((lid >> 4) << 3);
                uint32_t byte = (uint32_t)(rowb * 128 + ks * 32 + (((lid >> 3) & 1) << 4));
                uint32_t sw = byte ^ ((byte >> 3) & 0x70);
                uint32_t k0, k1, k2, k3;
                LDSM_X4(k0, k1, k2, k3, base + 0 + sw);
                MMA_F16(sacc[2*nj],   qf[ks], k0, k1);
                MMA_F16(sacc[2*nj+1], qf[ks], k2, k3);
            }
        }

        const int* mrow = msm + buf * 64;
        float mx0 = -1e30f, mx1 = -1e30f;
#pragma unroll
        for (int t = 0; t < 8; t++) {
            int cb = t * 8 + (lid & 3) * 2;
            bool k0 = mrow[cb] != 0, k1 = mrow[cb + 1] != 0;
            float s00 = k0 ? sacc[t][0] : -1e30f;
            float s01 = k1 ? sacc[t][1] : -1e30f;
            float s10 = k0 ? sacc[t][2] : -1e30f;
            float s11 = k1 ? sacc[t][3] : -1e30f;
            sacc[t][0] = s00; sacc[t][1] = s01; sacc[t][2] = s10; sacc[t][3] = s11;
            mx0 = fmaxf(mx0, fmaxf(s00, s01));
            mx1 = fmaxf(mx1, fmaxf(s10, s11));
        }
        mx0 = fmaxf(mx0, __shfl_xor_sync(0xffffffffu, mx0, 1));
        mx0 = fmaxf(mx0, __shfl_xor_sync(0xffffffffu, mx0, 2));
        mx1 = fmaxf(mx1, __shfl_xor_sync(0xffffffffu, mx1, 1));
        mx1 = fmaxf(mx1, __shfl_xor_sync(0xffffffffu, mx1, 2));

        float mn0 = fmaxf(rm0, mx0), mn1 = fmaxf(rm1, mx1);
        float sc0 = __expf(rm0 - mn0), sc1 = __expf(rm1 - mn1);
        rm0 = mn0; rm1 = mn1;
        float ps0 = 0.f, ps1 = 0.f;
#pragma unroll
        for (int t = 0; t < 8; t++) {
            float p00 = __expf(sacc[t][0] - mn0);
            float p01 = __expf(sacc[t][1] - mn0);
            float p10 = __expf(sacc[t][2] - mn1);
            float p11 = __expf(sacc[t][3] - mn1);
            sacc[t][0] = p00; sacc[t][1] = p01; sacc[t][2] = p10; sacc[t][3] = p11;
            ps0 += p00 + p01;
            ps1 += p10 + p11;
            ctx[t][0] *= sc0; ctx[t][1] *= sc0;
            ctx[t][2] *= sc1; ctx[t][3] *= sc1;
        }
        ps0 += __shfl_xor_sync(0xffffffffu, ps0, 1);
        ps0 += __shfl_xor_sync(0xffffffffu, ps0, 2);
        ps1 += __shfl_xor_sync(0xffffffffu, ps1, 1);
        ps1 += __shfl_xor_sync(0xffffffffu, ps1, 2);
        rl0 = rl0 * sc0 + ps0;
        rl1 = rl1 * sc1 + ps1;

        uint32_t pf[4][4];
#pragma unroll
        for (int j = 0; j < 4; j++) {
            pf[j][0] = pack_h2(sacc[2*j][0],   sacc[2*j][1]);
            pf[j][1] = pack_h2(sacc[2*j][2],   sacc[2*j][3]);
            pf[j][2] = pack_h2(sacc[2*j+1][0], sacc[2*j+1][1]);
            pf[j][3] = pack_h2(sacc[2*j+1][2], sacc[2*j+1][3]);
        }

#pragma unroll
        for (int ks = 0; ks < 4; ks++) {
#pragma unroll
            for (int nj = 0; nj < 4; nj++) {
                int rowb = nj * 16 + (lid & 7) + ((lid >> 4) << 3);
                uint32_t byte = (uint32_t)(rowb * 128 + ks * 32 + (((lid >> 3) & 1) << 4));
                uint32_t sw = byte ^ ((byte >> 3) & 0x70);
                uint32_t v0, v1, v2, v3;
                LDSM_X4(v0, v1, v2, v3, base + 8192 + sw);
                MMA_F16(ctx[2*nj],   pf[ks], v0, v1);
                MMA_F16(ctx[2*nj+1], pf[ks], v2, v3);
            }
        }
    }

    float inv0 = 1.f / rl0, inv1 = 1.f / rl1;
    int row = q0 + wid * 16 + (lid >> 2);
#pragma unroll
    for (int t = 0; t < 8; t++) {
        int col = h * HD_ + t * 8 + (lid & 3) * 2;
        *(float2*)(ctxout + (size_t)(b * SQ_ + row) * D_ + col) =
            make_float2(ctx[t][0] * inv0, ctx[t][1] * inv0);
        *(float2*)(ctxout + (size_t)(b * SQ_ + row + 8) * D_ + col) =
            make_float2(ctx[t][2] * inv1, ctx[t][3] * inv1);
    }
}

// ---------------------------------------------------------------------------
// fp32 -> fp16 elementwise, 2 sources selected by blockIdx.y
// ---------------------------------------------------------------------------
__global__ void __launch_bounds__(256) conv_h_kernel(
    const float4* __restrict__ s0, __half2* __restrict__ d0,
    const float4* __restrict__ s1, __half2* __restrict__ d1, int n4)
{
    int i = blockIdx.x * 256 + threadIdx.x;
    if (i >= n4) return;
    const float4* src = blockIdx.y ? s1 : s0;
    __half2* dst = blockIdx.y ? d1 : d0;
    float4 v = src[i];
    dst[2 * i]     = __floats2half2_rn(v.x, v.y);
    dst[2 * i + 1] = __floats2half2_rn(v.z, v.w);
}

// ---------------------------------------------------------------------------
// Weight transpose + fp16: W[K][N] -> Wt[N][K], 4 weights via blockIdx.z
// ---------------------------------------------------------------------------
__global__ void __launch_bounds__(256) conv_w_kernel(
    const float* __restrict__ W0, __half* __restrict__ T0,
    const float* __restrict__ W1, __half* __restrict__ T1,
    const float* __restrict__ W2, __half* __restrict__ T2,
    const float* __restrict__ W3, __half* __restrict__ T3)
{
    const float* W = (blockIdx.z == 0) ? W0 : (blockIdx.z == 1) ? W1 : (blockIdx.z == 2) ? W2 : W3;
    __half* T = (blockIdx.z == 0) ? T0 : (blockIdx.z == 1) ? T1 : (blockIdx.z == 2) ? T2 : T3;
    __shared__ float t[32][33];
    int n0 = blockIdx.x * 32, k0 = blockIdx.y * 32;
    int x = threadIdx.x, y = threadIdx.y;
#pragma unroll
    for (int i = y; i < 32; i += 8)
        t[i][x] = W[(size_t)(k0 + i) * D_ + n0 + x];
    __syncthreads();
#pragma unroll
    for (int r = y; r < 32; r += 8)
        T[(size_t)(n0 + r) * D_ + k0 + x] = __float2half(t[x][r]);
}

// ---------------------------------------------------------------------------
// V transpose + fp16: v fp32 [B,S,D] -> vt fp16 [B,H,64,Skv]
// ---------------------------------------------------------------------------
__global__ void __launch_bounds__(256) vtrans_kernel(
    const float* __restrict__ v, __half* __restrict__ vt)
{
    __shared__ float t[32][33];
    int b = blockIdx.z;
    int hh = blockIdx.y;
    int h = hh >> 1, hd0 = (hh & 1) * 32;
    int s0 = blockIdx.x * 32;
    int x = threadIdx.x, y = threadIdx.y;
#pragma unroll
    for (int i = y; i < 32; i += 8)
        t[i][x] = v[(size_t)(b * SQ_ + s0 + i) * D_ + h * HD_ + hd0 + x];
    __syncthreads();
#pragma unroll
    for (int r = y; r < 32; r += 8)
        vt[((size_t)(b * H_ + h) * HD_ + hd0 + r) * SKV_ + s0 + x] = __float2half(t[x][r]);
}

// ---------------------------------------------------------------------------
// LayerNorm kernels
// ---------------------------------------------------------------------------
__device__ __forceinline__ float block_reduce_sum_256(float val, float* sbuf)
{
    int lane = threadIdx.x & 31, w = threadIdx.x >> 5;
#pragma unroll
    for (int o = 16; o; o >>= 1) val += __shfl_xor_sync(0xffffffff, val, o);
    if (lane == 0) sbuf[w] = val;
    __syncthreads();
    float r = (threadIdx.x < 8) ? sbuf[threadIdx.x] : 0.f;
    if (w == 0) {
#pragma unroll
        for (int o = 4; o; o >>= 1) r += __shfl_xor_sync(0xffffffff, r, o);
        if (lane == 0) sbuf[0] = r;
    }
    __syncthreads();
    return sbuf[0];
}

__global__ void __launch_bounds__(256) ln_add_kernel(
    const float* __restrict__ a, const float* __restrict__ bsrc,
    const float* __restrict__ g, const float* __restrict__ beta,
    float* __restrict__ out, __half* __restrict__ outh)
{
    __shared__ float sbuf[8];
    size_t row = blockIdx.x;
    int t = threadIdx.x;
    const float* pa = a + row * 1024;
    const float* pb = bsrc + row * 1024;
    float x[4];
    float s = 0.f;
#pragma unroll
    for (int i = 0; i < 4; i++) { int idx = t + i * 256; x[i] = pa[idx] + pb[idx]; s += x[i]; }
    s = block_reduce_sum_256(s, sbuf);
    float mu = s * (1.f / 1024.f);
    float vv = 0.f;
#pragma unroll
    for (int i = 0; i < 4; i++) { float d = x[i] - mu; vv += d * d; }
    __syncthreads();
    vv = block_reduce_sum_256(vv, sbuf);
    float r = rsqrtf(vv * (1.f / 1024.f) + 1e-5f);
#pragma unroll
    for (int i = 0; i < 4; i++) {
        int idx = t + i * 256;
        float y = (x[i] - mu) * r * g[idx] + beta[idx];
        out[row * 1024 + idx] = y;
        outh[row * 1024 + idx] = __float2half(y);
    }
}

__global__ void __launch_bounds__(256) ln_gelu_kernel(
    const float* __restrict__ a, const float* __restrict__ bsrc,
    const float* __restrict__ g, const float* __restrict__ beta,
    float* __restrict__ out)
{
    __shared__ float sbuf[8];
    size_t row = blockIdx.x;
    int t = threadIdx.x;
    const float* pa = a + row * 1024;
    const float* pb = bsrc + row * 1024;
    float x[4];
    float s = 0.f;
#pragma unroll
    for (int i = 0; i < 4; i++) {
        int idx = t + i * 256;
        float hv = pb[idx];
        float ge = 0.5f * hv * (1.f + erff(hv * 0.70710678118654752f));
        x[i] = pa[idx] + ge;
        s += x[i];
    }
    s = block_reduce_sum_256(s, sbuf);
    float mu = s * (1.f / 1024.f);
    float vv = 0.f;
#pragma unroll
    for (int i = 0; i < 4; i++) { float d = x[i] - mu; vv += d * d; }
    __syncthreads();
    vv = block_reduce_sum_256(vv, sbuf);
    float r = rsqrtf(vv * (1.f / 1024.f) + 1e-5f);
    float* po = out + row * 1024;
#pragma unroll
    for (int i = 0; i < 4; i++) {
        int idx = t + i * 256;
        po[idx] = (x[i] - mu) * r * g[idx] + beta[idx];
    }
}

// ---------------------------------------------------------------------------
extern "C" void kernel_launch(void* const* d_in, const int* in_sizes, int n_in,
                              void* d_out, int out_size)
{
    const float* Q     = (const float*)d_in[0];
    const float* K     = (const float*)d_in[1];
    const int*   mask  = (const int*)d_in[2];
    const float* Wq    = (const float*)d_in[3];
    const float* bq    = (const float*)d_in[4];
    const float* Wk    = (const float*)d_in[5];
    const float* bk    = (const float*)d_in[6];
    const float* Wv    = (const float*)d_in[7];
    const float* bv    = (const float*)d_in[8];
    const float* Wp    = (const float*)d_in[9];
    const float* bp    = (const float*)d_in[10];
    const float* g0    = (const float*)d_in[11];
    const float* beta0 = (const float*)d_in[12];
    const float* g1    = (const float*)d_in[13];
    const float* beta1 = (const float*)d_in[14];
    float* out = (float*)d_out;

    float *q, *v, *ctx, *o1, *h;
    cudaGetSymbolAddress((void**)&q,   g_q);
    cudaGetSymbolAddress((void**)&v,   g_v);
    cudaGetSymbolAddress((void**)&ctx, g_ctx);
    cudaGetSymbolAddress((void**)&o1,  g_o1);
    cudaGetSymbolAddress((void**)&h,   g_h);

    __half *iq, *ik, *pq, *pk, *vt, *o1f, *wq, *wk, *wv, *wp;
    cudaGetSymbolAddress((void**)&iq,  g_iq);
    cudaGetSymbolAddress((void**)&ik,  g_ik);
    cudaGetSymbolAddress((void**)&pq,  g_pq);
    cudaGetSymbolAddress((void**)&pk,  g_pk);
    cudaGetSymbolAddress((void**)&vt,  g_vt);
    cudaGetSymbolAddress((void**)&o1f, g_o1f);
    cudaGetSymbolAddress((void**)&wq,  g_wq);
    cudaGetSymbolAddress((void**)&wk,  g_wk);
    cudaGetSymbolAddress((void**)&wv,  g_wv);
    cudaGetSymbolAddress((void**)&wp,  g_wp);

    cudaFuncSetAttribute(tgemm_kernel, cudaFuncAttributeMaxDynamicSharedMemorySize, GEMM_SMEM);
    cudaFuncSetAttribute(attn_mma_kernel, cudaFuncAttributeMaxDynamicSharedMemorySize, ATT_SMEM);

    const int n4 = MTOT * D_ / 4;
    dim3 cblk(256);
    dim3 cgrid(n4 / 256, 2);

    conv_h_kernel<<<cgrid, cblk>>>((const float4*)Q, (__half2*)iq,
                                   (const float4*)K, (__half2*)ik, n4);

    dim3 wgrid(32, 32, 4), wblk(32, 8);
    conv_w_kernel<<<wgrid, wblk>>>(Wq, wq, Wk, wk, Wv, wv, Wp, wp);

    dim3 ggrid(D_ / TN, MTOT / TM);   // (8, 64)
    tgemm_kernel<<<ggrid, 128, GEMM_SMEM>>>(iq, wq, bq, q, pq, 0.125f);
    tgemm_kernel<<<ggrid, 128, GEMM_SMEM>>>(ik, wk, bk, nullptr, pk, 1.0f);
    tgemm_kernel<<<ggrid, 128, GEMM_SMEM>>>(ik, wv, bv, v, nullptr, 1.0f);

    dim3 vtgrid(32, 32, 8);
    vtrans_kernel<<<vtgrid, wblk>>>(v, vt);

    dim3 agrid(SQ_ / 128, H_, B_);
    attn_mma_kernel<<<agrid, 256, ATT_SMEM>>>(pq, pk, vt, mask, ctx);

    ln_add_kernel<<<MTOT, 256>>>(q, ctx, g0, beta0, o1, o1f);

    tgemm_kernel<<<ggrid, 128, GEMM_SMEM>>>(o1f, wp, bp, h, nullptr, 1.0f);

    ln_gelu_kernel<<<MTOT, 256>>>(o1, h, g1, beta1, out);
}

// round 7
// speedup vs baseline: 8.2030x; 1.0357x over previous
#include <cuda_runtime.h>
#include <cuda_fp16.h>
#include <math.h>
#include <stdint.h>

#define B_ 8
#define SQ_ 1024
#define SKV_ 1024
#define D_ 1024
#define H_ 16
#define HD_ 64
#define MTOT (B_*SQ_)   // 8192

// ---------------- scratch (device globals; allocation-free rule) -----------
__device__ float g_q  [MTOT*D_];
__device__ float g_v  [MTOT*D_];
__device__ float g_ctx[MTOT*D_];
__device__ float g_o1 [MTOT*D_];
__device__ float g_h  [MTOT*D_];

__device__ __half g_iq[MTOT*D_];            // Q input fp16
__device__ __half g_ik[MTOT*D_];            // K input fp16
__device__ __half g_pq[MTOT*D_];            // projected q fp16 (pre-scaled by 1/8)
__device__ __half g_pk[MTOT*D_];            // projected k fp16
__device__ __half g_vt[MTOT*D_];            // V^T fp16 [B,H,64,Skv]
__device__ __half g_o1f[MTOT*D_];           // o1 fp16
__device__ __half g_wq[D_*D_], g_wk[D_*D_], g_wv[D_*D_], g_wp[D_*D_]; // W^T fp16

// ---------------- helpers ----------------------------------------------------
__device__ __forceinline__ uint32_t smem_to_u32(const void* p) {
    uint32_t a;
    asm("{ .reg .u64 t; cvta.to.shared.u64 t, %1; cvt.u32.u64 %0, t; }" : "=r"(a) : "l"(p));
    return a;
}
#define CP_ASYNC16(dst_u32, gptr) \
    asm volatile("cp.async.cg.shared.global [%0], [%1], 16;" :: "r"(dst_u32), "l"(gptr) : "memory")
#define CP_COMMIT() asm volatile("cp.async.commit_group;" ::: "memory")
#define CP_WAIT1()  asm volatile("cp.async.wait_group 1;" ::: "memory")
#define CP_WAIT0()  asm volatile("cp.async.wait_group 0;" ::: "memory")

#define LDSM_X4(r0,r1,r2,r3,addr) \
    asm volatile("ldmatrix.sync.aligned.m8n8.x4.shared.b16 {%0,%1,%2,%3}, [%4];" \
        : "=r"(r0),"=r"(r1),"=r"(r2),"=r"(r3) : "r"(addr))

#define MMA_F16(c, a, b0v, b1v) \
    asm volatile("mma.sync.aligned.m16n8k16.row.col.f32.f16.f16.f32 " \
        "{%0,%1,%2,%3}, {%4,%5,%6,%7}, {%8,%9}, {%0,%1,%2,%3};" \
        : "+f"((c)[0]),"+f"((c)[1]),"+f"((c)[2]),"+f"((c)[3]) \
        : "r"((a)[0]),"r"((a)[1]),"r"((a)[2]),"r"((a)[3]), "r"(b0v),"r"(b1v))

__device__ __forceinline__ uint32_t pack_h2(float x, float y) {
    __half2 t = __floats2half2_rn(x, y);
    return *reinterpret_cast<uint32_t*>(&t);
}

// ---------------------------------------------------------------------------
// GEMM body: C = A@W + bias. A fp16 [M][K]; W transposed fp16 [N][K].
// CTA tile 128x128, 4 warps (64x64 each), K-chunk 64, 3-stage cp.async.
// ---------------------------------------------------------------------------
#define TM 128
#define TN 128
#define TK 64
#define OFF_A 0
#define OFF_B 16384
#define STAGE_BYTES 32768
#define NSTAGE 3
#define SMEM_BUF0 1024
#define GEMM_SMEM (SMEM_BUF0 + NSTAGE*STAGE_BYTES)   // 99328

__device__ __forceinline__ void gemm_body(
    const __half* __restrict__ A, const __half* __restrict__ W,
    const float* __restrict__ bias, float* __restrict__ Cf,
    __half* __restrict__ Ch, float oscale,
    char* smem, int row0, int col0)
{
    uint32_t sb = smem_to_u32(smem);
    int tid = threadIdx.x, wid = tid >> 5, lid = tid & 31;

    auto load_chunk = [&](int buf, int kc) {
        uint32_t base = sb + SMEM_BUF0 + buf * STAGE_BYTES;
        int k0 = kc * TK;
#pragma unroll
        for (int i = 0; i < 8; i++) {
            int u = tid + i * 128;
            int r = u >> 3, c = u & 7;
            uint32_t byte = (uint32_t)(r * 128 + c * 16);
            uint32_t sw = byte ^ ((byte >> 3) & 0x70);
            CP_ASYNC16(base + OFF_A + sw, A + (size_t)(row0 + r) * D_ + k0 + c * 8);
            CP_ASYNC16(base + OFF_B + sw, W + (size_t)(col0 + r) * D_ + k0 + c * 8);
        }
    };

    int wm = wid & 1;      // 2 warps over M: 64 rows each
    int wn = wid >> 1;     // 2 warps over N: 64 cols each

    float acc[4][8][4];
#pragma unroll
    for (int i = 0; i < 4; i++)
#pragma unroll
        for (int j = 0; j < 8; j++)
#pragma unroll
            for (int e = 0; e < 4; e++) acc[i][j][e] = 0.f;

    load_chunk(0, 0); CP_COMMIT();
    load_chunk(1, 1); CP_COMMIT();

    for (int kc = 0; kc < 16; kc++) {
        int buf = kc % NSTAGE;
        CP_WAIT1();               // chunk kc resident (kc+1 may be in flight)
        __syncthreads();          // all warps done with buffer (kc+2)%3's prior contents
        if (kc + 2 < 16) load_chunk((kc + 2) % NSTAGE, kc + 2);
        CP_COMMIT();

        uint32_t base = sb + SMEM_BUF0 + buf * STAGE_BYTES;
        uint32_t sa = base + OFF_A, sw_ = base + OFF_B;

#pragma unroll
        for (int ks = 0; ks < 4; ks++) {
            uint32_t af[4][4];
#pragma unroll
            for (int mi = 0; mi < 4; mi++) {
                int rowa = wm * 64 + mi * 16 + (lid & 15);
                uint32_t byte = (uint32_t)(rowa * 128 + ks * 32 + ((lid >> 4) << 4));
                uint32_t sw = byte ^ ((byte >> 3) & 0x70);
                LDSM_X4(af[mi][0], af[mi][1], af[mi][2], af[mi][3], sa + sw);
            }
#pragma unroll
            for (int nj = 0; nj < 4; nj++) {
                int rowb = wn * 64 + nj * 16 + (lid & 7) + ((lid >> 4) << 3);
                uint32_t byte = (uint32_t)(rowb * 128 + ks * 32 + (((lid >> 3) & 1) << 4));
                uint32_t sw = byte ^ ((byte >> 3) & 0x70);
                uint32_t b0, b1, b2, b3;
                LDSM_X4(b0, b1, b2, b3, sw_ + sw);
#pragma unroll
                for (int mi = 0; mi < 4; mi++) {
                    MMA_F16(acc[mi][2*nj],   af[mi], b0, b1);
                    MMA_F16(acc[mi][2*nj+1], af[mi], b2, b3);
                }
            }
        }
    }

#pragma unroll
    for (int mi = 0; mi < 4; mi++) {
#pragma unroll
        for (int nj = 0; nj < 8; nj++) {
            int m = row0 + wm * 64 + mi * 16 + (lid >> 2);
            int n = col0 + wn * 64 + nj * 8 + (lid & 3) * 2;
            float bn0 = __ldg(bias + n), bn1 = __ldg(bias + n + 1);
            float v00 = acc[mi][nj][0] + bn0, v01 = acc[mi][nj][1] + bn1;
            float v10 = acc[mi][nj][2] + bn0, v11 = acc[mi][nj][3] + bn1;
            if (Cf) {
                *(float2*)(Cf + (size_t)m * D_ + n) = make_float2(v00, v01);
                *(float2*)(Cf + (size_t)(m + 8) * D_ + n) = make_float2(v10, v11);
            }
            if (Ch) {
                *(uint32_t*)(Ch + (size_t)m * D_ + n) = pack_h2(v00 * oscale, v01 * oscale);
                *(uint32_t*)(Ch + (size_t)(m + 8) * D_ + n) = pack_h2(v10 * oscale, v11 * oscale);
            }
        }
    }
}

// Fused q/k/v projections: blockIdx.z selects {q, k, v}
__global__ void __launch_bounds__(128, 2) tgemm_qkv_kernel(
    const __half* __restrict__ iq, const __half* __restrict__ ik,
    const __half* __restrict__ wq, const __half* __restrict__ wk,
    const __half* __restrict__ wv,
    const float* __restrict__ bq, const float* __restrict__ bk,
    const float* __restrict__ bv,
    float* __restrict__ qf, float* __restrict__ vf,
    __half* __restrict__ pq, __half* __restrict__ pk)
{
    extern __shared__ char smem[];
    int z = blockIdx.z;
    const __half* A = (z == 0) ? iq : ik;
    const __half* W = (z == 0) ? wq : (z == 1) ? wk : wv;
    const float* bias = (z == 0) ? bq : (z == 1) ? bk : bv;
    float* Cf = (z == 0) ? qf : (z == 2) ? vf : nullptr;
    __half* Ch = (z == 0) ? pq : (z == 1) ? pk : nullptr;
    float sc = (z == 0) ? 0.125f : 1.0f;
    gemm_body(A, W, bias, Cf, Ch, sc, smem, blockIdx.y * TM, blockIdx.x * TN);
}

// Single GEMM (output projection)
__global__ void __launch_bounds__(128, 2) tgemm_kernel(
    const __half* __restrict__ A, const __half* __restrict__ W,
    const float* __restrict__ bias, float* __restrict__ Cf)
{
    extern __shared__ char smem[];
    gemm_body(A, W, bias, Cf, nullptr, 1.0f, smem, blockIdx.y * TM, blockIdx.x * TN);
}

// ---------------------------------------------------------------------------
// Tensor-core flash attention (fp16 single-pass). CTA = 128 queries x (b,h).
// ---------------------------------------------------------------------------
#define AOFF_Q 0
#define AOFF_STAGE 16384
#define ASTAGE_BYTES 16384
#define ATT_SMEM (16384 + 2*16384 + 512)   // 49664

__global__ void __launch_bounds__(256, 2) attn_mma_kernel(
    const __half* __restrict__ pq, const __half* __restrict__ pk,
    const __half* __restrict__ vt, const int* __restrict__ mask,
    float* __restrict__ ctxout)
{
    extern __shared__ char smem[];
    uint32_t sb = smem_to_u32(smem);
    int* msm = (int*)(smem + AOFF_STAGE + 2 * ASTAGE_BYTES);   // [2][64]

    int b = blockIdx.z, h = blockIdx.y;
    int q0 = blockIdx.x * 128;
    int tid = threadIdx.x, wid = tid >> 5, lid = tid & 31;

#pragma unroll
    for (int i = 0; i < 4; i++) {
        int u = tid + i * 256;
        int r = u >> 3, c = u & 7;
        uint32_t byte = (uint32_t)(r * 128 + c * 16);
        uint32_t sw = byte ^ ((byte >> 3) & 0x70);
        CP_ASYNC16(sb + AOFF_Q + sw, pq + (size_t)(b * SQ_ + q0 + r) * D_ + h * HD_ + c * 8);
    }

    auto load_stage = [&](int buf, int kt) {
        uint32_t base = sb + AOFF_STAGE + buf * ASTAGE_BYTES;
        int kv0 = kt * 64;
#pragma unroll
        for (int i = 0; i < 2; i++) {
            int u = tid + i * 256;
            int r = u >> 3, c = u & 7;
            uint32_t byte = (uint32_t)(r * 128 + c * 16);
            uint32_t sw = byte ^ ((byte >> 3) & 0x70);
            CP_ASYNC16(base + 0    + sw, pk + (size_t)(b * SKV_ + kv0 + r) * D_ + h * HD_ + c * 8);
            CP_ASYNC16(base + 8192 + sw, vt + ((size_t)(b * H_ + h) * HD_ + r) * SKV_ + kv0 + c * 8);
        }
        if (tid < 64) msm[buf * 64 + tid] = mask[b * SKV_ + kv0 + tid];
    };

    load_stage(0, 0);
    CP_COMMIT();

    uint32_t qf[4][4];
    float ctx[8][4];
#pragma unroll
    for (int t = 0; t < 8; t++)
#pragma unroll
        for (int e = 0; e < 4; e++) ctx[t][e] = 0.f;
    float rm0 = -1e30f, rm1 = -1e30f, rl0 = 0.f, rl1 = 0.f;

    for (int kt = 0; kt < 16; kt++) {
        int buf = kt & 1;
        __syncthreads();
        if (kt + 1 < 16) { load_stage(buf ^ 1, kt + 1); CP_COMMIT(); CP_WAIT1(); }
        else             { CP_WAIT0(); }
        __syncthreads();

        if (kt == 0) {
#pragma unroll
            for (int ks = 0; ks < 4; ks++) {
                int rowa = wid * 16 + (lid & 15);
                uint32_t byte = (uint32_t)(rowa * 128 + ks * 32 + ((lid >> 4) << 4));
                uint32_t sw = byte ^ ((byte >> 3) & 0x70);
                LDSM_X4(qf[ks][0], qf[ks][1], qf[ks][2], qf[ks][3], sb + AOFF_Q + sw);
            }
        }

        uint32_t base = sb + AOFF_STAGE + buf * ASTAGE_BYTES;
        float sacc[8][4];
#pragma unroll
        for (int t = 0; t < 8; t++)
#pragma unroll
            for (int e = 0; e < 4; e++) sacc[t][e] = 0.f;

#pragma unroll
        for (int ks = 0; ks < 4; ks++) {
#pragma unroll
            for (int nj = 0; nj < 4; nj++) {
                int rowb = nj * 16 + (lid & 7) + ((lid >> 4) << 3);
                uint32_t byte = (uint32_t)(rowb * 128 + ks * 32 + (((lid >> 3) & 1) << 4));
                uint32_t sw = byte ^ ((byte >> 3) & 0x70);
                uint32_t k0, k1, k2, k3;
                LDSM_X4(k0, k1, k2, k3, base + 0 + sw);
                MMA_F16(sacc[2*nj],   qf[ks], k0, k1);
                MMA_F16(sacc[2*nj+1], qf[ks], k2, k3);
            }
        }

        const int* mrow = msm + buf * 64;
        float mx0 = -1e30f, mx1 = -1e30f;
#pragma unroll
        for (int t = 0; t < 8; t++) {
            int cb = t * 8 + (lid & 3) * 2;
            bool k0 = mrow[cb] != 0, k1 = mrow[cb + 1] != 0;
            float s00 = k0 ? sacc[t][0] : -1e30f;
            float s01 = k1 ? sacc[t][1] : -1e30f;
            float s10 = k0 ? sacc[t][2] : -1e30f;
            float s11 = k1 ? sacc[t][3] : -1e30f;
            sacc[t][0] = s00; sacc[t][1] = s01; sacc[t][2] = s10; sacc[t][3] = s11;
            mx0 = fmaxf(mx0, fmaxf(s00, s01));
            mx1 = fmaxf(mx1, fmaxf(s10, s11));
        }
        mx0 = fmaxf(mx0, __shfl_xor_sync(0xffffffffu, mx0, 1));
        mx0 = fmaxf(mx0, __shfl_xor_sync(0xffffffffu, mx0, 2));
        mx1 = fmaxf(mx1, __shfl_xor_sync(0xffffffffu, mx1, 1));
        mx1 = fmaxf(mx1, __shfl_xor_sync(0xffffffffu, mx1, 2));

        float mn0 = fmaxf(rm0, mx0), mn1 = fmaxf(rm1, mx1);
        float sc0 = __expf(rm0 - mn0), sc1 = __expf(rm1 - mn1);
        rm0 = mn0; rm1 = mn1;
        float ps0 = 0.f, ps1 = 0.f;
#pragma unroll
        for (int t = 0; t < 8; t++) {
            float p00 = __expf(sacc[t][0] - mn0);
            float p01 = __expf(sacc[t][1] - mn0);
            float p10 = __expf(sacc[t][2] - mn1);
            float p11 = __expf(sacc[t][3] - mn1);
            sacc[t][0] = p00; sacc[t][1] = p01; sacc[t][2] = p10; sacc[t][3] = p11;
            ps0 += p00 + p01;
            ps1 += p10 + p11;
            ctx[t][0] *= sc0; ctx[t][1] *= sc0;
            ctx[t][2] *= sc1; ctx[t][3] *= sc1;
        }
        ps0 += __shfl_xor_sync(0xffffffffu, ps0, 1);
        ps0 += __shfl_xor_sync(0xffffffffu, ps0, 2);
        ps1 += __shfl_xor_sync(0xffffffffu, ps1, 1);
        ps1 += __shfl_xor_sync(0xffffffffu, ps1, 2);
        rl0 = rl0 * sc0 + ps0;
        rl1 = rl1 * sc1 + ps1;

        uint32_t pf[4][4];
#pragma unroll
        for (int j = 0; j < 4; j++) {
            pf[j][0] = pack_h2(sacc[2*j][0],   sacc[2*j][1]);
            pf[j][1] = pack_h2(sacc[2*j][2],   sacc[2*j][3]);
            pf[j][2] = pack_h2(sacc[2*j+1][0], sacc[2*j+1][1]);
            pf[j][3] = pack_h2(sacc[2*j+1][2], sacc[2*j+1][3]);
        }

#pragma unroll
        for (int ks = 0; ks < 4; ks++) {
#pragma unroll
            for (int nj = 0; nj < 4; nj++) {
                int rowb = nj * 16 + (lid & 7) + ((lid >> 4) << 3);
                uint32_t byte = (uint32_t)(rowb * 128 + ks * 32 + (((lid >> 3) & 1) << 4));
                uint32_t sw = byte ^ ((byte >> 3) & 0x70);
                uint32_t v0, v1, v2, v3;
                LDSM_X4(v0, v1, v2, v3, base + 8192 + sw);
                MMA_F16(ctx[2*nj],   pf[ks], v0, v1);
                MMA_F16(ctx[2*nj+1], pf[ks], v2, v3);
            }
        }
    }

    float inv0 = 1.f / rl0, inv1 = 1.f / rl1;
    int row = q0 + wid * 16 + (lid >> 2);
#pragma unroll
    for (int t = 0; t < 8; t++) {
        int col = h * HD_ + t * 8 + (lid & 3) * 2;
        *(float2*)(ctxout + (size_t)(b * SQ_ + row) * D_ + col) =
            make_float2(ctx[t][0] * inv0, ctx[t][1] * inv0);
        *(float2*)(ctxout + (size_t)(b * SQ_ + row + 8) * D_ + col) =
            make_float2(ctx[t][2] * inv1, ctx[t][3] * inv1);
    }
}

// ---------------------------------------------------------------------------
// fp32 -> fp16 elementwise, 2 sources selected by blockIdx.y
// ---------------------------------------------------------------------------
__global__ void __launch_bounds__(256) conv_h_kernel(
    const float4* __restrict__ s0, __half2* __restrict__ d0,
    const float4* __restrict__ s1, __half2* __restrict__ d1, int n4)
{
    int i = blockIdx.x * 256 + threadIdx.x;
    if (i >= n4) return;
    const float4* src = blockIdx.y ? s1 : s0;
    __half2* dst = blockIdx.y ? d1 : d0;
    float4 v = src[i];
    dst[2 * i]     = __floats2half2_rn(v.x, v.y);
    dst[2 * i + 1] = __floats2half2_rn(v.z, v.w);
}

// ---------------------------------------------------------------------------
// Weight transpose + fp16: W[K][N] -> Wt[N][K], 4 weights via blockIdx.z
// ---------------------------------------------------------------------------
__global__ void __launch_bounds__(256) conv_w_kernel(
    const float* __restrict__ W0, __half* __restrict__ T0,
    const float* __restrict__ W1, __half* __restrict__ T1,
    const float* __restrict__ W2, __half* __restrict__ T2,
    const float* __restrict__ W3, __half* __restrict__ T3)
{
    const float* W = (blockIdx.z == 0) ? W0 : (blockIdx.z == 1) ? W1 : (blockIdx.z == 2) ? W2 : W3;
    __half* T = (blockIdx.z == 0) ? T0 : (blockIdx.z == 1) ? T1 : (blockIdx.z == 2) ? T2 : T3;
    __shared__ float t[32][33];
    int n0 = blockIdx.x * 32, k0 = blockIdx.y * 32;
    int x = threadIdx.x, y = threadIdx.y;
#pragma unroll
    for (int i = y; i < 32; i += 8)
        t[i][x] = W[(size_t)(k0 + i) * D_ + n0 + x];
    __syncthreads();
#pragma unroll
    for (int r = y; r < 32; r += 8)
        T[(size_t)(n0 + r) * D_ + k0 + x] = __float2half(t[x][r]);
}

// ---------------------------------------------------------------------------
// V transpose + fp16: v fp32 [B,S,D] -> vt fp16 [B,H,64,Skv]
// ---------------------------------------------------------------------------
__global__ void __launch_bounds__(256) vtrans_kernel(
    const float* __restrict__ v, __half* __restrict__ vt)
{
    __shared__ float t[32][33];
    int b = blockIdx.z;
    int hh = blockIdx.y;
    int h = hh >> 1, hd0 = (hh & 1) * 32;
    int s0 = blockIdx.x * 32;
    int x = threadIdx.x, y = threadIdx.y;
#pragma unroll
    for (int i = y; i < 32; i += 8)
        t[i][x] = v[(size_t)(b * SQ_ + s0 + i) * D_ + h * HD_ + hd0 + x];
    __syncthreads();
#pragma unroll
    for (int r = y; r < 32; r += 8)
        vt[((size_t)(b * H_ + h) * HD_ + hd0 + r) * SKV_ + s0 + x] = __float2half(t[x][r]);
}

// ---------------------------------------------------------------------------
// LayerNorm kernels
// ---------------------------------------------------------------------------
__device__ __forceinline__ float block_reduce_sum_256(float val, float* sbuf)
{
    int lane = threadIdx.x & 31, w = threadIdx.x >> 5;
#pragma unroll
    for (int o = 16; o; o >>= 1) val += __shfl_xor_sync(0xffffffff, val, o);
    if (lane == 0) sbuf[w] = val;
    __syncthreads();
    float r = (threadIdx.x < 8) ? sbuf[threadIdx.x] : 0.f;
    if (w == 0) {
#pragma unroll
        for (int o = 4; o; o >>= 1) r += __shfl_xor_sync(0xffffffff, r, o);
        if (lane == 0) sbuf[0] = r;
    }
    __syncthreads();
    return sbuf[0];
}

__global__ void __launch_bounds__(256) ln_add_kernel(
    const float* __restrict__ a, const float* __restrict__ bsrc,
    const float* __restrict__ g, const float* __restrict__ beta,
    float* __restrict__ out, __half* __restrict__ outh)
{
    __shared__ float sbuf[8];
    size_t row = blockIdx.x;
    int t = threadIdx.x;
    const float* pa = a + row * 1024;
    const float* pb = bsrc + row * 1024;
    float x[4];
    float s = 0.f;
#pragma unroll
    for (int i = 0; i < 4; i++) { int idx = t + i * 256; x[i] = pa[idx] + pb[idx]; s += x[i]; }
    s = block_reduce_sum_256(s, sbuf);
    float mu = s * (1.f / 1024.f);
    float vv = 0.f;
#pragma unroll
    for (int i = 0; i < 4; i++) { float d = x[i] - mu; vv += d * d; }
    __syncthreads();
    vv = block_reduce_sum_256(vv, sbuf);
    float r = rsqrtf(vv * (1.f / 1024.f) + 1e-5f);
#pragma unroll
    for (int i = 0; i < 4; i++) {
        int idx = t + i * 256;
        float y = (x[i] - mu) * r * g[idx] + beta[idx];
        out[row * 1024 + idx] = y;
        outh[row * 1024 + idx] = __float2half(y);
    }
}

__global__ void __launch_bounds__(256) ln_gelu_kernel(
    const float* __restrict__ a, const float* __restrict__ bsrc,
    const float* __restrict__ g, const float* __restrict__ beta,
    float* __restrict__ out)
{
    __shared__ float sbuf[8];
    size_t row = blockIdx.x;
    int t = threadIdx.x;
    const float* pa = a + row * 1024;
    const float* pb = bsrc + row * 1024;
    float x[4];
    float s = 0.f;
#pragma unroll
    for (int i = 0; i < 4; i++) {
        int idx = t + i * 256;
        float hv = pb[idx];
        float ge = 0.5f * hv * (1.f + erff(hv * 0.70710678118654752f));
        x[i] = pa[idx] + ge;
        s += x[i];
    }
    s = block_reduce_sum_256(s, sbuf);
    float mu = s * (1.f / 1024.f);
    float vv = 0.f;
#pragma unroll
    for (int i = 0; i < 4; i++) { float d = x[i] - mu; vv += d * d; }
    __syncthreads();
    vv = block_reduce_sum_256(vv, sbuf);
    float r = rsqrtf(vv * (1.f / 1024.f) + 1e-5f);
    float* po = out + row * 1024;
#pragma unroll
    for (int i = 0; i < 4; i++) {
        int idx = t + i * 256;
        po[idx] = (x[i] - mu) * r * g[idx] + beta[idx];
    }
}

// ---------------------------------------------------------------------------
extern "C" void kernel_launch(void* const* d_in, const int* in_sizes, int n_in,
                              void* d_out, int out_size)
{
    const float* Q     = (const float*)d_in[0];
    const float* K     = (const float*)d_in[1];
    const int*   mask  = (const int*)d_in[2];
    const float* Wq    = (const float*)d_in[3];
    const float* bq    = (const float*)d_in[4];
    const float* Wk    = (const float*)d_in[5];
    const float* bk    = (const float*)d_in[6];
    const float* Wv    = (const float*)d_in[7];
    const float* bv    = (const float*)d_in[8];
    const float* Wp    = (const float*)d_in[9];
    const float* bp    = (const float*)d_in[10];
    const float* g0    = (const float*)d_in[11];
    const float* beta0 = (const float*)d_in[12];
    const float* g1    = (const float*)d_in[13];
    const float* beta1 = (const float*)d_in[14];
    float* out = (float*)d_out;

    float *q, *v, *ctx, *o1, *h;
    cudaGetSymbolAddress((void**)&q,   g_q);
    cudaGetSymbolAddress((void**)&v,   g_v);
    cudaGetSymbolAddress((void**)&ctx, g_ctx);
    cudaGetSymbolAddress((void**)&o1,  g_o1);
    cudaGetSymbolAddress((void**)&h,   g_h);

    __half *iq, *ik, *pq, *pk, *vt, *o1f, *wq, *wk, *wv, *wp;
    cudaGetSymbolAddress((void**)&iq,  g_iq);
    cudaGetSymbolAddress((void**)&ik,  g_ik);
    cudaGetSymbolAddress((void**)&pq,  g_pq);
    cudaGetSymbolAddress((void**)&pk,  g_pk);
    cudaGetSymbolAddress((void**)&vt,  g_vt);
    cudaGetSymbolAddress((void**)&o1f, g_o1f);
    cudaGetSymbolAddress((void**)&wq,  g_wq);
    cudaGetSymbolAddress((void**)&wk,  g_wk);
    cudaGetSymbolAddress((void**)&wv,  g_wv);
    cudaGetSymbolAddress((void**)&wp,  g_wp);

    cudaFuncSetAttribute(tgemm_qkv_kernel, cudaFuncAttributeMaxDynamicSharedMemorySize, GEMM_SMEM);
    cudaFuncSetAttribute(tgemm_kernel, cudaFuncAttributeMaxDynamicSharedMemorySize, GEMM_SMEM);
    cudaFuncSetAttribute(attn_mma_kernel, cudaFuncAttributeMaxDynamicSharedMemorySize, ATT_SMEM);

    const int n4 = MTOT * D_ / 4;
    dim3 cblk(256);
    dim3 cgrid(n4 / 256, 2);

    conv_h_kernel<<<cgrid, cblk>>>((const float4*)Q, (__half2*)iq,
                                   (const float4*)K, (__half2*)ik, n4);

    dim3 wgrid(32, 32, 4), wblk(32, 8);
    conv_w_kernel<<<wgrid, wblk>>>(Wq, wq, Wk, wk, Wv, wv, Wp, wp);

    // Fused q/k/v projections: 1536 CTAs
    dim3 gqkv(D_ / TN, MTOT / TM, 3);
    tgemm_qkv_kernel<<<gqkv, 128, GEMM_SMEM>>>(iq, ik, wq, wk, wv, bq, bk, bv,
                                               q, v, pq, pk);

    dim3 vtgrid(32, 32, 8);
    vtrans_kernel<<<vtgrid, wblk>>>(v, vt);

    dim3 agrid(SQ_ / 128, H_, B_);
    attn_mma_kernel<<<agrid, 256, ATT_SMEM>>>(pq, pk, vt, mask, ctx);

    ln_add_kernel<<<MTOT, 256>>>(q, ctx, g0, beta0, o1, o1f);

    dim3 ggrid(D_ / TN, MTOT / TM);
    tgemm_kernel<<<ggrid, 128, GEMM_SMEM>>>(o1f, wp, bp, h);

    ln_gelu_kernel<<<MTOT, 256>>>(o1, h, g1, beta1, out);
}

// round 8
// speedup vs baseline: 8.3398x; 1.0167x over previous
#include <cuda_runtime.h>
#include <cuda_fp16.h>
#include <math.h>
#include <stdint.h>

#define B_ 8
#define SQ_ 1024
#define SKV_ 1024
#define D_ 1024
#define H_ 16
#define HD_ 64
#define MTOT (B_*SQ_)   // 8192

// ---------------- scratch (device globals; allocation-free rule) -----------
__device__ float g_q  [MTOT*D_];
__device__ float g_ctx[MTOT*D_];
__device__ float g_o1 [MTOT*D_];
__device__ float g_h  [MTOT*D_];

__device__ __half g_iq[MTOT*D_];            // Q input fp16
__device__ __half g_ik[MTOT*D_];            // K input fp16
__device__ __half g_pq[MTOT*D_];            // projected q fp16 (pre-scaled by 1/8)
__device__ __half g_pk[MTOT*D_];            // projected k fp16
__device__ __half g_vt[MTOT*D_];            // V^T fp16 [B,H,64,Skv]
__device__ __half g_o1f[MTOT*D_];           // o1 fp16
__device__ __half g_wq[D_*D_], g_wk[D_*D_], g_wv[D_*D_], g_wp[D_*D_]; // W^T fp16

// ---------------- helpers ----------------------------------------------------
__device__ __forceinline__ uint32_t smem_to_u32(const void* p) {
    uint32_t a;
    asm("{ .reg .u64 t; cvta.to.shared.u64 t, %1; cvt.u32.u64 %0, t; }" : "=r"(a) : "l"(p));
    return a;
}
#define CP_ASYNC16(dst_u32, gptr) \
    asm volatile("cp.async.cg.shared.global [%0], [%1], 16;" :: "r"(dst_u32), "l"(gptr) : "memory")
#define CP_COMMIT() asm volatile("cp.async.commit_group;" ::: "memory")
#define CP_WAIT1()  asm volatile("cp.async.wait_group 1;" ::: "memory")
#define CP_WAIT0()  asm volatile("cp.async.wait_group 0;" ::: "memory")

#define LDSM_X4(r0,r1,r2,r3,addr) \
    asm volatile("ldmatrix.sync.aligned.m8n8.x4.shared.b16 {%0,%1,%2,%3}, [%4];" \
        : "=r"(r0),"=r"(r1),"=r"(r2),"=r"(r3) : "r"(addr))

#define MMA_F16(c, a, b0v, b1v) \
    asm volatile("mma.sync.aligned.m16n8k16.row.col.f32.f16.f16.f32 " \
        "{%0,%1,%2,%3}, {%4,%5,%6,%7}, {%8,%9}, {%0,%1,%2,%3};" \
        : "+f"((c)[0]),"+f"((c)[1]),"+f"((c)[2]),"+f"((c)[3]) \
        : "r"((a)[0]),"r"((a)[1]),"r"((a)[2]),"r"((a)[3]), "r"(b0v),"r"(b1v))

__device__ __forceinline__ uint32_t pack_h2(float x, float y) {
    __half2 t = __floats2half2_rn(x, y);
    return *reinterpret_cast<uint32_t*>(&t);
}

// ---------------------------------------------------------------------------
// GEMM body: C = A@W + bias. A fp16 [M][K]; W transposed fp16 [N][K].
// CTA tile 128x128, 4 warps (64x64 each), K-chunk 64, 3-stage cp.async.
// Outputs: fp32 Cf and/or fp16 Ch (scaled), and/or fp16 transposed VtOut
// (Vt layout [B,H,64,Skv], via smem transpose, coalesced).
// ---------------------------------------------------------------------------
#define TM 128
#define TN 128
#define TK 64
#define OFF_A 0
#define OFF_B 16384
#define STAGE_BYTES 32768
#define NSTAGE 3
#define SMEM_BUF0 1024
#define GEMM_SMEM (SMEM_BUF0 + NSTAGE*STAGE_BYTES)   // 99328
#define TP 136   // padded row stride (halves) for transpose buffer

__device__ __forceinline__ void gemm_body(
    const __half* __restrict__ A, const __half* __restrict__ W,
    const float* __restrict__ bias, float* __restrict__ Cf,
    __half* __restrict__ Ch, float oscale, __half* __restrict__ VtOut,
    char* smem, int row0, int col0)
{
    uint32_t sb = smem_to_u32(smem);
    int tid = threadIdx.x, wid = tid >> 5, lid = tid & 31;

    auto load_chunk = [&](int buf, int kc) {
        uint32_t base = sb + SMEM_BUF0 + buf * STAGE_BYTES;
        int k0 = kc * TK;
#pragma unroll
        for (int i = 0; i < 8; i++) {
            int u = tid + i * 128;
            int r = u >> 3, c = u & 7;
            uint32_t byte = (uint32_t)(r * 128 + c * 16);
            uint32_t sw = byte ^ ((byte >> 3) & 0x70);
            CP_ASYNC16(base + OFF_A + sw, A + (size_t)(row0 + r) * D_ + k0 + c * 8);
            CP_ASYNC16(base + OFF_B + sw, W + (size_t)(col0 + r) * D_ + k0 + c * 8);
        }
    };

    int wm = wid & 1;      // 2 warps over M: 64 rows each
    int wn = wid >> 1;     // 2 warps over N: 64 cols each

    float acc[4][8][4];
#pragma unroll
    for (int i = 0; i < 4; i++)
#pragma unroll
        for (int j = 0; j < 8; j++)
#pragma unroll
            for (int e = 0; e < 4; e++) acc[i][j][e] = 0.f;

    load_chunk(0, 0); CP_COMMIT();
    load_chunk(1, 1); CP_COMMIT();

    for (int kc = 0; kc < 16; kc++) {
        int buf = kc % NSTAGE;
        CP_WAIT1();
        __syncthreads();
        if (kc + 2 < 16) load_chunk((kc + 2) % NSTAGE, kc + 2);
        CP_COMMIT();

        uint32_t base = sb + SMEM_BUF0 + buf * STAGE_BYTES;
        uint32_t sa = base + OFF_A, sw_ = base + OFF_B;

#pragma unroll
        for (int ks = 0; ks < 4; ks++) {
            uint32_t af[4][4];
#pragma unroll
            for (int mi = 0; mi < 4; mi++) {
                int rowa = wm * 64 + mi * 16 + (lid & 15);
                uint32_t byte = (uint32_t)(rowa * 128 + ks * 32 + ((lid >> 4) << 4));
                uint32_t sw = byte ^ ((byte >> 3) & 0x70);
                LDSM_X4(af[mi][0], af[mi][1], af[mi][2], af[mi][3], sa + sw);
            }
#pragma unroll
            for (int nj = 0; nj < 4; nj++) {
                int rowb = wn * 64 + nj * 16 + (lid & 7) + ((lid >> 4) << 3);
                uint32_t byte = (uint32_t)(rowb * 128 + ks * 32 + (((lid >> 3) & 1) << 4));
                uint32_t sw = byte ^ ((byte >> 3) & 0x70);
                uint32_t b0, b1, b2, b3;
                LDSM_X4(b0, b1, b2, b3, sw_ + sw);
#pragma unroll
                for (int mi = 0; mi < 4; mi++) {
                    MMA_F16(acc[mi][2*nj],   af[mi], b0, b1);
                    MMA_F16(acc[mi][2*nj+1], af[mi], b2, b3);
                }
            }
        }
    }

    if (VtOut) {
        // ---- transposed fp16 epilogue: stage [n][m] in smem, write Vt ----
        __syncthreads();   // all warps done reading stage buffers
        __half* st = (__half*)(smem + SMEM_BUF0);
#pragma unroll
        for (int mi = 0; mi < 4; mi++) {
#pragma unroll
            for (int nj = 0; nj < 8; nj++) {
                int m = wm * 64 + mi * 16 + (lid >> 2);
                int n = wn * 64 + nj * 8 + (lid & 3) * 2;
                float bn0 = __ldg(bias + col0 + n), bn1 = __ldg(bias + col0 + n + 1);
                st[(size_t)n * TP + m]           = __float2half(acc[mi][nj][0] + bn0);
                st[(size_t)(n + 1) * TP + m]     = __float2half(acc[mi][nj][1] + bn1);
                st[(size_t)n * TP + m + 8]       = __float2half(acc[mi][nj][2] + bn0);
                st[(size_t)(n + 1) * TP + m + 8] = __float2half(acc[mi][nj][3] + bn1);
            }
        }
        __syncthreads();
        int b = row0 >> 10, s0 = row0 & 1023;
        // each warp writes 2 rows per iter (16 lanes per row of 128 halves)
        for (int rr = wid * 2; rr < 128; rr += 8) {
            int r = rr + (lid >> 4);
            int ng = col0 + r;
            int hh = ng >> 6, hd = ng & 63;
            uint4 val = *(uint4*)(st + (size_t)r * TP + (lid & 15) * 8);
            *(uint4*)(VtOut + ((size_t)(b * H_ + hh) * HD_ + hd) * SKV_ + s0 + (lid & 15) * 8) = val;
        }
        return;
    }

#pragma unroll
    for (int mi = 0; mi < 4; mi++) {
#pragma unroll
        for (int nj = 0; nj < 8; nj++) {
            int m = row0 + wm * 64 + mi * 16 + (lid >> 2);
            int n = col0 + wn * 64 + nj * 8 + (lid & 3) * 2;
            float bn0 = __ldg(bias + n), bn1 = __ldg(bias + n + 1);
            float v00 = acc[mi][nj][0] + bn0, v01 = acc[mi][nj][1] + bn1;
            float v10 = acc[mi][nj][2] + bn0, v11 = acc[mi][nj][3] + bn1;
            if (Cf) {
                *(float2*)(Cf + (size_t)m * D_ + n) = make_float2(v00, v01);
                *(float2*)(Cf + (size_t)(m + 8) * D_ + n) = make_float2(v10, v11);
            }
            if (Ch) {
                *(uint32_t*)(Ch + (size_t)m * D_ + n) = pack_h2(v00 * oscale, v01 * oscale);
                *(uint32_t*)(Ch + (size_t)(m + 8) * D_ + n) = pack_h2(v10 * oscale, v11 * oscale);
            }
        }
    }
}

// Fused q/k/v projections: blockIdx.z selects {q, k, v}
__global__ void __launch_bounds__(128, 2) tgemm_qkv_kernel(
    const __half* __restrict__ iq, const __half* __restrict__ ik,
    const __half* __restrict__ wq, const __half* __restrict__ wk,
    const __half* __restrict__ wv,
    const float* __restrict__ bq, const float* __restrict__ bk,
    const float* __restrict__ bv,
    float* __restrict__ qf,
    __half* __restrict__ pq, __half* __restrict__ pk,
    __half* __restrict__ vt)
{
    extern __shared__ char smem[];
    int z = blockIdx.z;
    const __half* A = (z == 0) ? iq : ik;
    const __half* W = (z == 0) ? wq : (z == 1) ? wk : wv;
    const float* bias = (z == 0) ? bq : (z == 1) ? bk : bv;
    float* Cf = (z == 0) ? qf : nullptr;
    __half* Ch = (z == 0) ? pq : (z == 1) ? pk : nullptr;
    __half* Vt = (z == 2) ? vt : nullptr;
    float sc = (z == 0) ? 0.125f : 1.0f;
    gemm_body(A, W, bias, Cf, Ch, sc, Vt, smem, blockIdx.y * TM, blockIdx.x * TN);
}

// Single GEMM (output projection)
__global__ void __launch_bounds__(128, 2) tgemm_kernel(
    const __half* __restrict__ A, const __half* __restrict__ W,
    const float* __restrict__ bias, float* __restrict__ Cf)
{
    extern __shared__ char smem[];
    gemm_body(A, W, bias, Cf, nullptr, 1.0f, nullptr, smem, blockIdx.y * TM, blockIdx.x * TN);
}

// ---------------------------------------------------------------------------
// Tensor-core flash attention (fp16 single-pass). CTA = 128 queries x (b,h).
// ---------------------------------------------------------------------------
#define AOFF_Q 0
#define AOFF_STAGE 16384
#define ASTAGE_BYTES 16384
#define ATT_SMEM (16384 + 2*16384 + 512)   // 49664

__global__ void __launch_bounds__(256, 2) attn_mma_kernel(
    const __half* __restrict__ pq, const __half* __restrict__ pk,
    const __half* __restrict__ vt, const int* __restrict__ mask,
    float* __restrict__ ctxout)
{
    extern __shared__ char smem[];
    uint32_t sb = smem_to_u32(smem);
    int* msm = (int*)(smem + AOFF_STAGE + 2 * ASTAGE_BYTES);   // [2][64]

    int b = blockIdx.z, h = blockIdx.y;
    int q0 = blockIdx.x * 128;
    int tid = threadIdx.x, wid = tid >> 5, lid = tid & 31;

#pragma unroll
    for (int i = 0; i < 4; i++) {
        int u = tid + i * 256;
        int r = u >> 3, c = u & 7;
        uint32_t byte = (uint32_t)(r * 128 + c * 16);
        uint32_t sw = byte ^ ((byte >> 3) & 0x70);
        CP_ASYNC16(sb + AOFF_Q + sw, pq + (size_t)(b * SQ_ + q0 + r) * D_ + h * HD_ + c * 8);
    }

    auto load_stage = [&](int buf, int kt) {
        uint32_t base = sb + AOFF_STAGE + buf * ASTAGE_BYTES;
        int kv0 = kt * 64;
#pragma unroll
        for (int i = 0; i < 2; i++) {
            int u = tid + i * 256;
            int r = u >> 3, c = u & 7;
            uint32_t byte = (uint32_t)(r * 128 + c * 16);
            uint32_t sw = byte ^ ((byte >> 3) & 0x70);
            CP_ASYNC16(base + 0    + sw, pk + (size_t)(b * SKV_ + kv0 + r) * D_ + h * HD_ + c * 8);
            CP_ASYNC16(base + 8192 + sw, vt + ((size_t)(b * H_ + h) * HD_ + r) * SKV_ + kv0 + c * 8);
        }
        if (tid < 64) msm[buf * 64 + tid] = mask[b * SKV_ + kv0 + tid];
    };

    load_stage(0, 0);
    CP_COMMIT();

    uint32_t qf[4][4];
    float ctx[8][4];
#pragma unroll
    for (int t = 0; t < 8; t++)
#pragma unroll
        for (int e = 0; e < 4; e++) ctx[t][e] = 0.f;
    float rm0 = -1e30f, rm1 = -1e30f, rl0 = 0.f, rl1 = 0.f;

    for (int kt = 0; kt < 16; kt++) {
        int buf = kt & 1;
        __syncthreads();
        if (kt + 1 < 16) { load_stage(buf ^ 1, kt + 1); CP_COMMIT(); CP_WAIT1(); }
        else             { CP_WAIT0(); }
        __syncthreads();

        if (kt == 0) {
#pragma unroll
            for (int ks = 0; ks < 4; ks++) {
                int rowa = wid * 16 + (lid & 15);
                uint32_t byte = (uint32_t)(rowa * 128 + ks * 32 + ((lid >> 4) << 4));
                uint32_t sw = byte ^ ((byte >> 3) & 0x70);
                LDSM_X4(qf[ks][0], qf[ks][1], qf[ks][2], qf[ks][3], sb + AOFF_Q + sw);
            }
        }

        uint32_t base = sb + AOFF_STAGE + buf * ASTAGE_BYTES;
        float sacc[8][4];
#pragma unroll
        for (int t = 0; t < 8; t++)
#pragma unroll
            for (int e = 0; e < 4; e++) sacc[t][e] = 0.f;

#pragma unroll
        for (int ks = 0; ks < 4; ks++) {
#pragma unroll
            for (int nj = 0; nj < 4; nj++) {
                int rowb = nj * 16 + (lid & 7) + ((lid >> 4) << 3);
                uint32_t byte = (uint32_t)(rowb * 128 + ks * 32 + (((lid >> 3) & 1) << 4));
                uint32_t sw = byte ^ ((byte >> 3) & 0x70);
                uint32_t k0, k1, k2, k3;
                LDSM_X4(k0, k1, k2, k3, base + 0 + sw);
                MMA_F16(sacc[2*nj],   qf[ks], k0, k1);
                MMA_F16(sacc[2*nj+1], qf[ks], k2, k3);
            }
        }

        const int* mrow = msm + buf * 64;
        float mx0 = -1e30f, mx1 = -1e30f;
#pragma unroll
        for (int t = 0; t < 8; t++) {
            int cb = t * 8 + (lid & 3) * 2;
            bool k0 = mrow[cb] != 0, k1 = mrow[cb + 1] != 0;
            float s00 = k0 ? sacc[t][0] : -1e30f;
            float s01 = k1 ? sacc[t][1] : -1e30f;
            float s10 = k0 ? sacc[t][2] : -1e30f;
            float s11 = k1 ? sacc[t][3] : -1e30f;
            sacc[t][0] = s00; sacc[t][1] = s01; sacc[t][2] = s10; sacc[t][3] = s11;
            mx0 = fmaxf(mx0, fmaxf(s00, s01));
            mx1 = fmaxf(mx1, fmaxf(s10, s11));
        }
        mx0 = fmaxf(mx0, __shfl_xor_sync(0xffffffffu, mx0, 1));
        mx0 = fmaxf(mx0, __shfl_xor_sync(0xffffffffu, mx0, 2));
        mx1 = fmaxf(mx1, __shfl_xor_sync(0xffffffffu, mx1, 1));
        mx1 = fmaxf(mx1, __shfl_xor_sync(0xffffffffu, mx1, 2));

        float mn0 = fmaxf(rm0, mx0), mn1 = fmaxf(rm1, mx1);
        float sc0 = __expf(rm0 - mn0), sc1 = __expf(rm1 - mn1);
        rm0 = mn0; rm1 = mn1;
        float ps0 = 0.f, ps1 = 0.f;
#pragma unroll
        for (int t = 0; t < 8; t++) {
            float p00 = __expf(sacc[t][0] - mn0);
            float p01 = __expf(sacc[t][1] - mn0);
            float p10 = __expf(sacc[t][2] - mn1);
            float p11 = __expf(sacc[t][3] - mn1);
            sacc[t][0] = p00; sacc[t][1] = p01; sacc[t][2] = p10; sacc[t][3] = p11;
            ps0 += p00 + p01;
            ps1 += p10 + p11;
            ctx[t][0] *= sc0; ctx[t][1] *= sc0;
            ctx[t][2] *= sc1; ctx[t][3] *= sc1;
        }
        ps0 += __shfl_xor_sync(0xffffffffu, ps0, 1);
        ps0 += __shfl_xor_sync(0xffffffffu, ps0, 2);
        ps1 += __shfl_xor_sync(0xffffffffu, ps1, 1);
        ps1 += __shfl_xor_sync(0xffffffffu, ps1, 2);
        rl0 = rl0 * sc0 + ps0;
        rl1 = rl1 * sc1 + ps1;

        uint32_t pf[4][4];
#pragma unroll
        for (int j = 0; j < 4; j++) {
            pf[j][0] = pack_h2(sacc[2*j][0],   sacc[2*j][1]);
            pf[j][1] = pack_h2(sacc[2*j][2],   sacc[2*j][3]);
            pf[j][2] = pack_h2(sacc[2*j+1][0], sacc[2*j+1][1]);
            pf[j][3] = pack_h2(sacc[2*j+1][2], sacc[2*j+1][3]);
        }

#pragma unroll
        for (int ks = 0; ks < 4; ks++) {
#pragma unroll
            for (int nj = 0; nj < 4; nj++) {
                int rowb = nj * 16 + (lid & 7) + ((lid >> 4) << 3);
                uint32_t byte = (uint32_t)(rowb * 128 + ks * 32 + (((lid >> 3) & 1) << 4));
                uint32_t sw = byte ^ ((byte >> 3) & 0x70);
                uint32_t v0, v1, v2, v3;
                LDSM_X4(v0, v1, v2, v3, base + 8192 + sw);
                MMA_F16(ctx[2*nj],   pf[ks], v0, v1);
                MMA_F16(ctx[2*nj+1], pf[ks], v2, v3);
            }
        }
    }

    float inv0 = 1.f / rl0, inv1 = 1.f / rl1;
    int row = q0 + wid * 16 + (lid >> 2);
#pragma unroll
    for (int t = 0; t < 8; t++) {
        int col = h * HD_ + t * 8 + (lid & 3) * 2;
        *(float2*)(ctxout + (size_t)(b * SQ_ + row) * D_ + col) =
            make_float2(ctx[t][0] * inv0, ctx[t][1] * inv0);
        *(float2*)(ctxout + (size_t)(b * SQ_ + row + 8) * D_ + col) =
            make_float2(ctx[t][2] * inv1, ctx[t][3] * inv1);
    }
}

// ---------------------------------------------------------------------------
// fp32 -> fp16 elementwise, 2 sources selected by blockIdx.y
// ---------------------------------------------------------------------------
__global__ void __launch_bounds__(256) conv_h_kernel(
    const float4* __restrict__ s0, __half2* __restrict__ d0,
    const float4* __restrict__ s1, __half2* __restrict__ d1, int n4)
{
    int i = blockIdx.x * 256 + threadIdx.x;
    if (i >= n4) return;
    const float4* src = blockIdx.y ? s1 : s0;
    __half2* dst = blockIdx.y ? d1 : d0;
    float4 v = src[i];
    dst[2 * i]     = __floats2half2_rn(v.x, v.y);
    dst[2 * i + 1] = __floats2half2_rn(v.z, v.w);
}

// ---------------------------------------------------------------------------
// Weight transpose + fp16: W[K][N] -> Wt[N][K], 4 weights via blockIdx.z
// ---------------------------------------------------------------------------
__global__ void __launch_bounds__(256) conv_w_kernel(
    const float* __restrict__ W0, __half* __restrict__ T0,
    const float* __restrict__ W1, __half* __restrict__ T1,
    const float* __restrict__ W2, __half* __restrict__ T2,
    const float* __restrict__ W3, __half* __restrict__ T3)
{
    const float* W = (blockIdx.z == 0) ? W0 : (blockIdx.z == 1) ? W1 : (blockIdx.z == 2) ? W2 : W3;
    __half* T = (blockIdx.z == 0) ? T0 : (blockIdx.z == 1) ? T1 : (blockIdx.z == 2) ? T2 : T3;
    __shared__ float t[32][33];
    int n0 = blockIdx.x * 32, k0 = blockIdx.y * 32;
    int x = threadIdx.x, y = threadIdx.y;
#pragma unroll
    for (int i = y; i < 32; i += 8)
        t[i][x] = W[(size_t)(k0 + i) * D_ + n0 + x];
    __syncthreads();
#pragma unroll
    for (int r = y; r < 32; r += 8)
        T[(size_t)(n0 + r) * D_ + k0 + x] = __float2half(t[x][r]);
}

// ---------------------------------------------------------------------------
// LayerNorm kernels
// ---------------------------------------------------------------------------
__device__ __forceinline__ float block_reduce_sum_256(float val, float* sbuf)
{
    int lane = threadIdx.x & 31, w = threadIdx.x >> 5;
#pragma unroll
    for (int o = 16; o; o >>= 1) val += __shfl_xor_sync(0xffffffff, val, o);
    if (lane == 0) sbuf[w] = val;
    __syncthreads();
    float r = (threadIdx.x < 8) ? sbuf[threadIdx.x] : 0.f;
    if (w == 0) {
#pragma unroll
        for (int o = 4; o; o >>= 1) r += __shfl_xor_sync(0xffffffff, r, o);
        if (lane == 0) sbuf[0] = r;
    }
    __syncthreads();
    return sbuf[0];
}

__global__ void __launch_bounds__(256) ln_add_kernel(
    const float* __restrict__ a, const float* __restrict__ bsrc,
    const float* __restrict__ g, const float* __restrict__ beta,
    float* __restrict__ out, __half* __restrict__ outh)
{
    __shared__ float sbuf[8];
    size_t row = blockIdx.x;
    int t = threadIdx.x;
    const float* pa = a + row * 1024;
    const float* pb = bsrc + row * 1024;
    float x[4];
    float s = 0.f;
#pragma unroll
    for (int i = 0; i < 4; i++) { int idx = t + i * 256; x[i] = pa[idx] + pb[idx]; s += x[i]; }
    s = block_reduce_sum_256(s, sbuf);
    float mu = s * (1.f / 1024.f);
    float vv = 0.f;
#pragma unroll
    for (int i = 0; i < 4; i++) { float d = x[i] - mu; vv += d * d; }
    __syncthreads();
    vv = block_reduce_sum_256(vv, sbuf);
    float r = rsqrtf(vv * (1.f / 1024.f) + 1e-5f);
#pragma unroll
    for (int i = 0; i < 4; i++) {
        int idx = t + i * 256;
        float y = (x[i] - mu) * r * g[idx] + beta[idx];
        out[row * 1024 + idx] = y;
        outh[row * 1024 + idx] = __float2half(y);
    }
}

__global__ void __launch_bounds__(256) ln_gelu_kernel(
    const float* __restrict__ a, const float* __restrict__ bsrc,
    const float* __restrict__ g, const float* __restrict__ beta,
    float* __restrict__ out)
{
    __shared__ float sbuf[8];
    size_t row = blockIdx.x;
    int t = threadIdx.x;
    const float* pa = a + row * 1024;
    const float* pb = bsrc + row * 1024;
    float x[4];
    float s = 0.f;
#pragma unroll
    for (int i = 0; i < 4; i++) {
        int idx = t + i * 256;
        float hv = pb[idx];
        float ge = 0.5f * hv * (1.f + erff(hv * 0.70710678118654752f));
        x[i] = pa[idx] + ge;
        s += x[i];
    }
    s = block_reduce_sum_256(s, sbuf);
    float mu = s * (1.f / 1024.f);
    float vv = 0.f;
#pragma unroll
    for (int i = 0; i < 4; i++) { float d = x[i] - mu; vv += d * d; }
    __syncthreads();
    vv = block_reduce_sum_256(vv, sbuf);
    float r = rsqrtf(vv * (1.f / 1024.f) + 1e-5f);
    float* po = out + row * 1024;
#pragma unroll
    for (int i = 0; i < 4; i++) {
        int idx = t + i * 256;
        po[idx] = (x[i] - mu) * r * g[idx] + beta[idx];
    }
}

// ---------------------------------------------------------------------------
extern "C" void kernel_launch(void* const* d_in, const int* in_sizes, int n_in,
                              void* d_out, int out_size)
{
    const float* Q     = (const float*)d_in[0];
    const float* K     = (const float*)d_in[1];
    const int*   mask  = (const int*)d_in[2];
    const float* Wq    = (const float*)d_in[3];
    const float* bq    = (const float*)d_in[4];
    const float* Wk    = (const float*)d_in[5];
    const float* bk    = (const float*)d_in[6];
    const float* Wv    = (const float*)d_in[7];
    const float* bv    = (const float*)d_in[8];
    const float* Wp    = (const float*)d_in[9];
    const float* bp    = (const float*)d_in[10];
    const float* g0    = (const float*)d_in[11];
    const float* beta0 = (const float*)d_in[12];
    const float* g1    = (const float*)d_in[13];
    const float* beta1 = (const float*)d_in[14];
    float* out = (float*)d_out;

    float *q, *ctx, *o1, *h;
    cudaGetSymbolAddress((void**)&q,   g_q);
    cudaGetSymbolAddress((void**)&ctx, g_ctx);
    cudaGetSymbolAddress((void**)&o1,  g_o1);
    cudaGetSymbolAddress((void**)&h,   g_h);

    __half *iq, *ik, *pq, *pk, *vt, *o1f, *wq, *wk, *wv, *wp;
    cudaGetSymbolAddress((void**)&iq,  g_iq);
    cudaGetSymbolAddress((void**)&ik,  g_ik);
    cudaGetSymbolAddress((void**)&pq,  g_pq);
    cudaGetSymbolAddress((void**)&pk,  g_pk);
    cudaGetSymbolAddress((void**)&vt,  g_vt);
    cudaGetSymbolAddress((void**)&o1f, g_o1f);
    cudaGetSymbolAddress((void**)&wq,  g_wq);
    cudaGetSymbolAddress((void**)&wk,  g_wk);
    cudaGetSymbolAddress((void**)&wv,  g_wv);
    cudaGetSymbolAddress((void**)&wp,  g_wp);

    cudaFuncSetAttribute(tgemm_qkv_kernel, cudaFuncAttributeMaxDynamicSharedMemorySize, GEMM_SMEM);
    cudaFuncSetAttribute(tgemm_kernel, cudaFuncAttributeMaxDynamicSharedMemorySize, GEMM_SMEM);
    cudaFuncSetAttribute(attn_mma_kernel, cudaFuncAttributeMaxDynamicSharedMemorySize, ATT_SMEM);

    const int n4 = MTOT * D_ / 4;
    dim3 cblk(256);
    dim3 cgrid(n4 / 256, 2);

    conv_h_kernel<<<cgrid, cblk>>>((const float4*)Q, (__half2*)iq,
                                   (const float4*)K, (__half2*)ik, n4);

    dim3 wgrid(32, 32, 4), wblk(32, 8);
    conv_w_kernel<<<wgrid, wblk>>>(Wq, wq, Wk, wk, Wv, wv, Wp, wp);

    // Fused q/k/v projections (V emits V^T fp16 directly)
    dim3 gqkv(D_ / TN, MTOT / TM, 3);
    tgemm_qkv_kernel<<<gqkv, 128, GEMM_SMEM>>>(iq, ik, wq, wk, wv, bq, bk, bv,
                                               q, pq, pk, vt);

    dim3 agrid(SQ_ / 128, H_, B_);
    attn_mma_kernel<<<agrid, 256, ATT_SMEM>>>(pq, pk, vt, mask, ctx);

    ln_add_kernel<<<MTOT, 256>>>(q, ctx, g0, beta0, o1, o1f);

    dim3 ggrid(D_ / TN, MTOT / TM);
    tgemm_kernel<<<ggrid, 128, GEMM_SMEM>>>(o1f, wp, bp, h);

    ln_gelu_kernel<<<MTOT, 256>>>(o1, h, g1, beta1, out);
}